// round 12
// baseline (speedup 1.0000x reference)
#include <cuda_runtime.h>
#include <cuda_fp16.h>
#include <math.h>
#include <stdint.h>

// ---------------- problem constants ----------------
#define BATCH 2
#define SEQ   1024
#define HDIM  2048
#define NHEAD 16
#define NKVH  4
#define HEADD 128
#define FFN   4096
#define NEXP  8
#define NTOK  (BATCH*SEQ)
#define QKVN  (NHEAD*HEADD + 2*NKVH*HEADD)   // 3072
#define NSLOT (2*NTOK)
#define LNEPS 1e-5f

// ---------------- device scratch ----------------
__device__ __half g_xln1h[NTOK*HDIM];
__device__ __half g_qkvh [NTOK*QKVN];
__device__ __half g_attnh[NTOK*NHEAD*HEADD];
__device__ float  g_h    [NTOK*HDIM];
__device__ float  g_xln2 [NTOK*HDIM];
__device__ __half g_xln2h[NTOK*HDIM];
__device__ __half g_acth [NSLOT*FFN];
__device__ float  g_eo   [NSLOT*HDIM];
// fp16 weights, ORIGINAL [K][N] layout
__device__ __half g_wqh [HDIM*NHEAD*HEADD];
__device__ __half g_wkh [HDIM*NKVH*HEADD];
__device__ __half g_wvh [HDIM*NKVH*HEADD];
__device__ __half g_woh [HDIM*HDIM];
__device__ __half g_w1h [NEXP*HDIM*FFN];
__device__ __half g_w3h [NEXP*HDIM*FFN];
__device__ __half g_w2h [NEXP*FFN*HDIM];
__device__ float  g_bqkv[QKVN];
// routing
__device__ int   g_e01 [NTOK*2];
__device__ float g_w01 [NTOK*2];
__device__ int   g_pos01[NTOK*2];
__device__ int   g_counts[NEXP];
__device__ int   g_offsets[NEXP];
__device__ int   g_toklist[NSLOT];
__device__ int   g_slot01[NTOK*2];

// ---------------- helpers ----------------
__device__ __forceinline__ void mma_f16(float* c, const uint32_t* a, const uint32_t* b){
    asm volatile(
      "mma.sync.aligned.m16n8k16.row.col.f32.f16.f16.f32 "
      "{%0,%1,%2,%3}, {%4,%5,%6,%7}, {%8,%9}, {%0,%1,%2,%3};\n"
      : "+f"(c[0]), "+f"(c[1]), "+f"(c[2]), "+f"(c[3])
      : "r"(a[0]), "r"(a[1]), "r"(a[2]), "r"(a[3]), "r"(b[0]), "r"(b[1]));
}
__device__ __forceinline__ void ldsm_x4(uint32_t& r0, uint32_t& r1, uint32_t& r2, uint32_t& r3,
                                        uint32_t addr){
    asm volatile("ldmatrix.sync.aligned.m8n8.x4.shared.b16 {%0,%1,%2,%3}, [%4];"
                 : "=r"(r0), "=r"(r1), "=r"(r2), "=r"(r3) : "r"(addr));
}
__device__ __forceinline__ void ldsm_x4_t(uint32_t& r0, uint32_t& r1, uint32_t& r2, uint32_t& r3,
                                          uint32_t addr){
    asm volatile("ldmatrix.sync.aligned.m8n8.x4.trans.shared.b16 {%0,%1,%2,%3}, [%4];"
                 : "=r"(r0), "=r"(r1), "=r"(r2), "=r"(r3) : "r"(addr));
}
__device__ __forceinline__ void cpa16h(__half* smem, const __half* gmem, bool pred){
    uint32_t s = (uint32_t)__cvta_generic_to_shared(smem);
    int sz = pred ? 16 : 0;
    asm volatile("cp.async.cg.shared.global [%0], [%1], 16, %2;\n"
                 :: "r"(s), "l"(gmem), "r"(sz));
}
#define CP_COMMIT() asm volatile("cp.async.commit_group;\n")
template<int N> __device__ __forceinline__ void cp_wait(){
    asm volatile("cp.async.wait_group %0;\n" :: "n"(N));
}

__device__ __forceinline__ float block_sum_256(float v){
    __shared__ float red[8];
    __shared__ float total;
    #pragma unroll
    for (int o = 16; o; o >>= 1) v += __shfl_xor_sync(0xffffffffu, v, o);
    if ((threadIdx.x & 31) == 0) red[threadIdx.x >> 5] = v;
    __syncthreads();
    if (threadIdx.x == 0){
        float s = 0.f;
        #pragma unroll
        for (int i = 0; i < 8; i++) s += red[i];
        total = s;
    }
    __syncthreads();
    float r = total;
    __syncthreads();
    return r;
}

// ---------------- streaming fp32 -> fp16 convert ----------------
__global__ __launch_bounds__(256)
void cvt16(const float4* __restrict__ src, uint4* __restrict__ dst, long long n8){
    for (long long i = blockIdx.x*256LL + threadIdx.x; i < n8; i += gridDim.x*256LL){
        float4 v0 = src[2*i], v1 = src[2*i+1];
        __half2 a = __floats2half2_rn(v0.x, v0.y);
        __half2 b = __floats2half2_rn(v0.z, v0.w);
        __half2 c = __floats2half2_rn(v1.x, v1.y);
        __half2 d = __floats2half2_rn(v1.z, v1.w);
        uint4 o;
        o.x = *(uint32_t*)&a; o.y = *(uint32_t*)&b;
        o.z = *(uint32_t*)&c; o.w = *(uint32_t*)&d;
        dst[i] = o;
    }
}

__global__ void concat_bias(const float* bq, const float* bk, const float* bv, float* dst){
    int i = blockIdx.x*256 + threadIdx.x;
    if (i < NHEAD*HEADD) dst[i] = bq[i];
    else if (i < NHEAD*HEADD + NKVH*HEADD) dst[i] = bk[i - NHEAD*HEADD];
    else if (i < QKVN) dst[i] = bv[i - NHEAD*HEADD - NKVH*HEADD];
}

// ---------------- LayerNorm ----------------
__global__ __launch_bounds__(256)
void ln_kernel(const float* __restrict__ x, const float* __restrict__ w,
               const float* __restrict__ b,
               float* __restrict__ yraw, __half* __restrict__ yh){
    long long row = blockIdx.x;
    const float* xr = x + row * HDIM;
    float v[8]; float s = 0.f;
    #pragma unroll
    for (int i = 0; i < 8; i++){ v[i] = xr[threadIdx.x + 256*i]; s += v[i]; }
    float mean = block_sum_256(s) * (1.f/HDIM);
    float ss = 0.f;
    #pragma unroll
    for (int i = 0; i < 8; i++){ float d = v[i]-mean; ss += d*d; }
    float var = block_sum_256(ss) * (1.f/HDIM);
    float rstd = rsqrtf(var + LNEPS);
    #pragma unroll
    for (int i = 0; i < 8; i++){
        int c = threadIdx.x + 256*i;
        float o = (v[i]-mean)*rstd*w[c] + b[c];
        if (yraw) yraw[row*HDIM + c] = o;
        yh[row*HDIM + c] = __float2half(o);
    }
}

// ---------------- fp16 GEMM: ldmatrix A + ldmatrix.trans B ----------------
// paired mode: each CTA computes 128 cols of B0 (h1) + matching 128 cols of B1 (h3),
// and writes act = silu(h1)*h3 (fp16) via smem exchange in the epilogue.
struct GemmSegs {
    int end[3];
    const __half* B[3];
    int ldb[3];
};

#define GA_STG (128*40)
#define GB_STG (32*264)
#define GB_BASE (3*GA_STG)
#define GEMM_SMEM_BYTES ((GB_BASE + 3*GB_STG)*2)   // 81408 >= 64KB exch

__global__ __launch_bounds__(256)
void gemm_f16(const __half* __restrict__ A, int lda,
              GemmSegs segs, long long bStride,
              float* __restrict__ Cf, __half* __restrict__ Ch, int ldc,
              const float* __restrict__ bias, const float* __restrict__ resid,
              int M, int K, int paired,
              const int* __restrict__ rowidx,
              const int* __restrict__ counts,
              const int* __restrict__ offsets)
{
    extern __shared__ __half hsm[];
#define ASH(st, r, c) hsm[(st)*GA_STG + (r)*40 + (c)]
#define BSH(st, k, c) hsm[GB_BASE + (st)*GB_STG + (k)*264 + (c)]

    int e = blockIdx.z;
    int rowStart = 0, Mm = M;
    if (counts){ Mm = counts[e]; rowStart = offsets[e]; }
    int mbase = blockIdx.y * 128;
    if (mbase >= Mm) return;

    int tid  = threadIdx.x;
    int lane = tid & 31, wid = tid >> 5;
    int warpM = wid >> 2, warpN = wid & 3;
    int g = lane >> 2, t4 = lane & 3;
    int brow = tid >> 3, bch = tid & 7;

    // B pointers per 16B-chunk index
    int nbase = 0, ldb;
    const __half* bptr[4];
    if (paired){
        int nb = blockIdx.x * 128;
        ldb = segs.ldb[0];
        const __half* B0p = segs.B[0] + (long long)e*bStride + nb;
        const __half* B1p = segs.B[1] + (long long)e*bStride + nb;
        #pragma unroll
        for (int i = 0; i < 4; i++){
            int c8 = (bch + 8*i)*8;
            bptr[i] = (c8 < 128) ? (B0p + c8) : (B1p + c8 - 128);
        }
    } else {
        nbase = blockIdx.x * 256;
        int s = 0;
        if (nbase >= segs.end[0]) s = 1;
        if (nbase >= segs.end[1]) s = 2;
        int segStart = (s == 0) ? 0 : segs.end[s-1];
        ldb = segs.ldb[s];
        const __half* Bp = segs.B[s] + (long long)e*bStride + (nbase - segStart);
        #pragma unroll
        for (int i = 0; i < 4; i++)
            bptr[i] = Bp + (bch + 8*i)*8;
    }

    int ar = tid >> 1, hsel = tid & 1;
    bool aval = (mbase + ar < Mm);
    int arow = 0;
    if (aval) arow = rowidx ? rowidx[rowStart + mbase + ar] : (rowStart + mbase + ar);
    const __half* aptr = A + (long long)arow * lda + hsel*16;

    uint32_t smbase = (uint32_t)__cvta_generic_to_shared(hsm);
    int a_m = (lane & 7) + 8*((lane >> 3) & 1);
    int a_k = 8*((lane >> 4) & 1);
    uint32_t asm0 = smbase + (uint32_t)((warpM*64 + a_m)*40 + a_k)*2;
    int k_off = (lane & 7) + 8*((lane >> 3) & 1);
    int c_off = warpN*64 + 8*((lane >> 4) & 1);
    uint32_t bsm0 = smbase + GB_BASE*2 + (uint32_t)(k_off*264 + c_off)*2;

    float acc[32][4];
    #pragma unroll
    for (int i = 0; i < 32; i++)
        #pragma unroll
        for (int j = 0; j < 4; j++) acc[i][j] = 0.f;

    int nk = K >> 5;

#define GEMM_ISSUE(KT, ST) do {                                               \
        cpa16h(&ASH(ST, ar, hsel*16),     aptr + (KT)*32,     aval);          \
        cpa16h(&ASH(ST, ar, hsel*16 + 8), aptr + (KT)*32 + 8, aval);          \
        _Pragma("unroll")                                                     \
        for (int i = 0; i < 4; i++){                                          \
            int c8 = (bch + 8*i)*8;                                           \
            cpa16h(&BSH(ST, brow, c8),                                        \
                   bptr[i] + (long long)((KT)*32 + brow)*ldb, true);          \
        }                                                                     \
    } while(0)

    GEMM_ISSUE(0, 0); CP_COMMIT();
    GEMM_ISSUE(1, 1); CP_COMMIT();

    int cur = 0;
    for (int kt = 0; kt < nk; ++kt){
        if (kt + 1 < nk) cp_wait<1>(); else cp_wait<0>();
        __syncthreads();
        if (kt + 2 < nk){
            int nxt = cur + 2; if (nxt >= 3) nxt -= 3;
            GEMM_ISSUE(kt+2, nxt); CP_COMMIT();
        }

        #pragma unroll
        for (int ks = 0; ks < 2; ++ks){
            uint32_t af[4][4], bf[8][2];
            uint32_t aadr = asm0 + (uint32_t)cur*(GA_STG*2) + (uint32_t)(ks*16*2);
            #pragma unroll
            for (int ma = 0; ma < 4; ma++){
                ldsm_x4(af[ma][0], af[ma][1], af[ma][2], af[ma][3],
                        aadr + (uint32_t)(ma*16*40*2));
            }
            uint32_t badr = bsm0 + (uint32_t)cur*(GB_STG*2) + (uint32_t)(ks*16*264*2);
            #pragma unroll
            for (int p = 0; p < 4; p++){
                ldsm_x4_t(bf[2*p][0], bf[2*p][1], bf[2*p+1][0], bf[2*p+1][1],
                          badr + (uint32_t)(p*16*2));
            }
            #pragma unroll
            for (int ma = 0; ma < 4; ma++)
                #pragma unroll
                for (int na = 0; na < 8; na++)
                    mma_f16(acc[ma*8+na], af[ma], bf[na]);
        }
        cur = cur + 1; if (cur >= 3) cur -= 3;
    }

    if (!paired){
        #pragma unroll
        for (int ma = 0; ma < 4; ma++){
            #pragma unroll
            for (int na = 0; na < 8; na++){
                float* a4 = acc[ma*8+na];
                #pragma unroll
                for (int half_ = 0; half_ < 2; half_++){
                    int lrow = warpM*64 + ma*16 + g + (half_ ? 8 : 0);
                    int gcol = nbase + warpN*64 + na*8 + 2*t4;
                    int gr = mbase + lrow;
                    if (gr < Mm){
                        long long orow = rowStart + gr;
                        float v0 = a4[half_*2+0];
                        float v1 = a4[half_*2+1];
                        if (bias){ v0 += bias[gcol]; v1 += bias[gcol+1]; }
                        if (resid){
                            const float* rp = &resid[orow*(long long)ldc + gcol];
                            v0 += rp[0]; v1 += rp[1];
                        }
                        if (Cf){
                            *(float2*)&Cf[orow*(long long)ldc + gcol] = make_float2(v0, v1);
                        } else {
                            *(__half2*)&Ch[orow*(long long)ldc + gcol] = __floats2half2_rn(v0, v1);
                        }
                    }
                }
            }
        }
    } else {
        // paired epilogue: warps with warpN>=2 hold h3; exchange via smem, h1 warps write act
        __syncthreads();           // all cp.async/smem use done; reuse hsm
        float* exch = (float*)hsm; // 128 x 128 floats = 64 KB
        int isH3 = warpN >> 1;
        int colBase = (warpN & 1)*64;
        if (isH3){
            #pragma unroll
            for (int ma = 0; ma < 4; ma++)
                #pragma unroll
                for (int na = 0; na < 8; na++){
                    float* a4 = acc[ma*8+na];
                    #pragma unroll
                    for (int half_ = 0; half_ < 2; half_++){
                        int lrow = warpM*64 + ma*16 + g + (half_ ? 8 : 0);
                        int lcol = colBase + na*8 + 2*t4;
                        exch[lrow*128 + lcol    ] = a4[half_*2+0];
                        exch[lrow*128 + lcol + 1] = a4[half_*2+1];
                    }
                }
        }
        __syncthreads();
        if (!isH3){
            int nb = blockIdx.x * 128;
            #pragma unroll
            for (int ma = 0; ma < 4; ma++)
                #pragma unroll
                for (int na = 0; na < 8; na++){
                    float* a4 = acc[ma*8+na];
                    #pragma unroll
                    for (int half_ = 0; half_ < 2; half_++){
                        int lrow = warpM*64 + ma*16 + g + (half_ ? 8 : 0);
                        int lcol = colBase + na*8 + 2*t4;
                        int gr = mbase + lrow;
                        if (gr < Mm){
                            long long orow = rowStart + gr;
                            float v0 = a4[half_*2+0];
                            float v1 = a4[half_*2+1];
                            float u0 = exch[lrow*128 + lcol    ];
                            float u1 = exch[lrow*128 + lcol + 1];
                            float r0 = v0 / (1.f + expf(-v0)) * u0;
                            float r1 = v1 / (1.f + expf(-v1)) * u1;
                            *(__half2*)&Ch[orow*(long long)ldc + nb + lcol] =
                                __floats2half2_rn(r0, r1);
                        }
                    }
                }
        }
    }
#undef ASH
#undef BSH
#undef GEMM_ISSUE
}

// ---------------- RoPE ----------------
__global__ __launch_bounds__(256)
void rope_kernel(__half* __restrict__ qkv, const int* __restrict__ pos_ids){
    int idx = blockIdx.x*256 + threadIdx.x;
    const int total = NTOK*(NHEAD+NKVH)*64;
    if (idx >= total) return;
    int j    = idx & 63;
    int rest = idx >> 6;
    int head = rest % (NHEAD+NKVH);
    int t    = rest / (NHEAD+NKVH);
    __half* p;
    if (head < NHEAD) p = qkv + (long long)t*QKVN + head*HEADD;
    else              p = qkv + (long long)t*QKVN + NHEAD*HEADD + (head-NHEAD)*HEADD;
    double inv = exp((double)j * -0.21586735246819178);
    float th = (float)pos_ids[t] * (float)inv;
    float sn, cs; sincosf(th, &sn, &cs);
    float x0 = __half2float(p[j]), x1 = __half2float(p[j+64]);
    p[j]    = __float2half(x0*cs - x1*sn);
    p[j+64] = __float2half(x1*cs + x0*sn);
}

// ---------------- fp16 tensor-core flash attention ----------------
#define FKT 32
#define FL_PS_F   (64*36)
#define FL_FLOATS (FL_PS_F + 64*3 + 32)
#define FL_QS_H   0
#define FL_KS_H   (FL_QS_H + 64*136)
#define FL_VS_H   (FL_KS_H + FKT*136)
#define FL_PH_H   (FL_VS_H + FKT*136)
#define FL_HALVES (FL_PH_H + 64*40)
#define FL_SMEM_BYTES (FL_FLOATS*4 + FL_HALVES*2)

__global__ __launch_bounds__(256, 2)
void flash_kernel(const __half* __restrict__ qkv, const int* __restrict__ amask,
                  __half* __restrict__ O)
{
    extern __shared__ float sm[];
    float* Ps   = sm;
    float* mrow = sm + FL_PS_F;
    float* lrow = mrow + 64;
    float* srow = lrow + 64;
    int*   mk   = (int*)(srow + 64);
    __half* hb  = (__half*)(sm + FL_FLOATS);
    __half* Qs = hb + FL_QS_H;
    __half* Ks = hb + FL_KS_H;
    __half* Vs = hb + FL_VS_H;
    __half* Ph = hb + FL_PH_H;

    int qt = blockIdx.x;
    int bh = blockIdx.y;
    int b  = bh >> 4, h = bh & 15;
    int kvh = h >> 2;
    int tid = threadIdx.x;
    int lane = tid & 31, wid = tid >> 5;
    int g = lane >> 2, t4 = lane & 3;
    int mS = wid & 3;
    int nH = wid >> 2;

    int vk = (lane & 7) + 8*((lane >> 3) & 1);
    int vc = 8*((lane >> 4) & 1);
    uint32_t vbase = (uint32_t)__cvta_generic_to_shared(Vs) + (uint32_t)(vk*136 + 64*nH + vc)*2;

    for (int e2 = tid; e2 < 64*64; e2 += 256){
        int row = e2 >> 6; int d2 = (e2 & 63)*2;
        *(uint32_t*)&Qs[row*136 + d2] =
            *(const uint32_t*)&qkv[(long long)(b*SEQ + qt*64 + row)*QKVN + h*HEADD + d2];
    }
    if (tid < 64){ mrow[tid] = -1e30f; lrow[tid] = 0.f; }

    float oacc[8][4];
    #pragma unroll
    for (int i = 0; i < 8; i++)
        #pragma unroll
        for (int j = 0; j < 4; j++) oacc[i][j] = 0.f;

    const float iscale = 0.08838834764831843f;

    int nkt = 2*qt + 2;
    for (int kt = 0; kt < nkt; ++kt){
        __syncthreads();
        for (int e2 = tid; e2 < FKT*64; e2 += 256){
            int kk = e2 >> 6; int d2 = (e2 & 63)*2;
            long long base = (long long)(b*SEQ + kt*FKT + kk)*QKVN + NHEAD*HEADD + kvh*HEADD;
            *(uint32_t*)&Ks[kk*136 + d2] = *(const uint32_t*)&qkv[base + d2];
            *(uint32_t*)&Vs[kk*136 + d2] = *(const uint32_t*)&qkv[base + NKVH*HEADD + d2];
        }
        if (tid < FKT) mk[tid] = amask[b*SEQ + kt*FKT + tid];
        __syncthreads();

        float sacc[2][4];
        #pragma unroll
        for (int i = 0; i < 2; i++)
            #pragma unroll
            for (int j = 0; j < 4; j++) sacc[i][j] = 0.f;
        #pragma unroll
        for (int ks = 0; ks < 8; ++ks){
            int k0 = ks*16;
            uint32_t a[4];
            int r = 16*mS;
            a[0] = *(const uint32_t*)&Qs[(r+g  )*136 + k0 + 2*t4    ];
            a[1] = *(const uint32_t*)&Qs[(r+g+8)*136 + k0 + 2*t4    ];
            a[2] = *(const uint32_t*)&Qs[(r+g  )*136 + k0 + 2*t4 + 8];
            a[3] = *(const uint32_t*)&Qs[(r+g+8)*136 + k0 + 2*t4 + 8];
            #pragma unroll
            for (int j = 0; j < 2; j++){
                int c = 16*nH + 8*j + g;
                uint32_t bfr[2];
                bfr[0] = *(const uint32_t*)&Ks[c*136 + k0 + 2*t4    ];
                bfr[1] = *(const uint32_t*)&Ks[c*136 + k0 + 2*t4 + 8];
                mma_f16(sacc[j], a, bfr);
            }
        }
        #pragma unroll
        for (int j = 0; j < 2; j++){
            #pragma unroll
            for (int cr = 0; cr < 4; cr++){
                int row = 16*mS + g + ((cr >= 2) ? 8 : 0);
                int col = 16*nH + 8*j + 2*t4 + (cr & 1);
                int sq = qt*64 + row, sk = kt*FKT + col;
                float vv = sacc[j][cr]*iscale;
                if (sk > sq || mk[col] == 0) vv = -1e30f;
                Ps[row*36 + col] = vv;
            }
        }
        __syncthreads();

        if (tid < 64){
            int r = tid;
            float mo = mrow[r], mx = mo;
            #pragma unroll 8
            for (int kk = 0; kk < FKT; kk++) mx = fmaxf(mx, Ps[r*36+kk]);
            float sc = __expf(mo - mx);
            float ssum = 0.f;
            #pragma unroll 8
            for (int kk = 0; kk < FKT; kk++){
                float p = __expf(Ps[r*36+kk] - mx);
                ssum += p;
                Ph[r*40+kk] = __float2half(p);
            }
            lrow[r] = lrow[r]*sc + ssum;
            mrow[r] = mx;
            srow[r] = sc;
        }
        __syncthreads();

        {
            float sc0 = srow[16*mS + g];
            float sc1 = srow[16*mS + g + 8];
            #pragma unroll
            for (int j = 0; j < 8; j++){
                oacc[j][0] *= sc0; oacc[j][1] *= sc0;
                oacc[j][2] *= sc1; oacc[j][3] *= sc1;
            }
        }
        #pragma unroll
        for (int ks = 0; ks < 2; ++ks){
            int k0 = ks*16 + 2*t4;
            uint32_t a[4];
            int r = 16*mS;
            a[0] = *(const uint32_t*)&Ph[(r+g  )*40 + k0    ];
            a[1] = *(const uint32_t*)&Ph[(r+g+8)*40 + k0    ];
            a[2] = *(const uint32_t*)&Ph[(r+g  )*40 + k0 + 8];
            a[3] = *(const uint32_t*)&Ph[(r+g+8)*40 + k0 + 8];
            uint32_t badr = vbase + (uint32_t)(ks*16*136*2);
            uint32_t bf[8][2];
            #pragma unroll
            for (int p = 0; p < 4; p++){
                ldsm_x4_t(bf[2*p][0], bf[2*p][1], bf[2*p+1][0], bf[2*p+1][1],
                          badr + (uint32_t)(p*16*2));
            }
            #pragma unroll
            for (int j = 0; j < 8; j++)
                mma_f16(oacc[j], a, bf[j]);
        }
    }

    #pragma unroll
    for (int j = 0; j < 8; j++){
        #pragma unroll
        for (int half_ = 0; half_ < 2; half_++){
            int row = 16*mS + g + (half_ ? 8 : 0);
            int col = 64*nH + 8*j + 2*t4;
            int sq = qt*64 + row;
            float inv = 1.f / lrow[row];
            __half2 o2 = __floats2half2_rn(oacc[j][half_*2+0]*inv, oacc[j][half_*2+1]*inv);
            *(__half2*)&O[(((long long)(b*SEQ + sq))*NHEAD + h)*HEADD + col] = o2;
        }
    }
}

// ---------------- gate + top2 (raw fp32) ----------------
__global__ __launch_bounds__(256)
void gate_kernel(const float* __restrict__ x2, const float* __restrict__ gw,
                 int* __restrict__ e01, float* __restrict__ w01){
    long long t = blockIdx.x;
    const float* xr = x2 + t*HDIM;
    float part[NEXP];
    #pragma unroll
    for (int e = 0; e < NEXP; e++) part[e] = 0.f;
    for (int hh = threadIdx.x; hh < HDIM; hh += 256){
        float xv = xr[hh];
        const float* gp = gw + (long long)hh*NEXP;
        #pragma unroll
        for (int e = 0; e < NEXP; e++) part[e] += xv*gp[e];
    }
    __shared__ float red[8][NEXP];
    #pragma unroll
    for (int e = 0; e < NEXP; e++){
        float v = part[e];
        #pragma unroll
        for (int o = 16; o; o >>= 1) v += __shfl_xor_sync(0xffffffffu, v, o);
        if ((threadIdx.x & 31) == 0) red[threadIdx.x >> 5][e] = v;
    }
    __syncthreads();
    if (threadIdx.x == 0){
        float lg[NEXP];
        #pragma unroll
        for (int e = 0; e < NEXP; e++){
            float s = 0.f;
            #pragma unroll
            for (int w8 = 0; w8 < 8; w8++) s += red[w8][e];
            lg[e] = s;
        }
        int b0 = 0;
        #pragma unroll
        for (int e = 1; e < NEXP; e++) if (lg[e] > lg[b0]) b0 = e;
        int b1 = -1;
        #pragma unroll
        for (int e = 0; e < NEXP; e++)
            if (e != b0 && (b1 < 0 || lg[e] > lg[b1])) b1 = e;
        float t0 = 1.f / (1.f + expf(lg[b1] - lg[b0]));
        e01[2*t] = b0; e01[2*t+1] = b1;
        w01[2*t] = t0; w01[2*t+1] = 1.f - t0;
    }
}

// ---------------- routing ----------------
__global__ void route_count_kernel(const int* __restrict__ e01,
                                   int* __restrict__ counts, int* __restrict__ pos01){
    int t = blockIdx.x*blockDim.x + threadIdx.x;
    if (t < NTOK){
        pos01[2*t]   = atomicAdd(&counts[e01[2*t]],   1);
        pos01[2*t+1] = atomicAdd(&counts[e01[2*t+1]], 1);
    }
}
__global__ void route_offset_kernel(const int* __restrict__ counts, int* __restrict__ offsets){
    if (threadIdx.x == 0 && blockIdx.x == 0){
        int s = 0;
        for (int e = 0; e < NEXP; e++){ offsets[e] = s; s += counts[e]; }
    }
}
__global__ void route_scatter_kernel(const int* __restrict__ e01, const int* __restrict__ pos01,
                                     const int* __restrict__ offsets,
                                     int* __restrict__ toklist, int* __restrict__ slot01){
    int t = blockIdx.x*blockDim.x + threadIdx.x;
    if (t < NTOK){
        #pragma unroll
        for (int j = 0; j < 2; j++){
            int sl = offsets[e01[2*t+j]] + pos01[2*t+j];
            toklist[sl] = t;
            slot01[2*t+j] = sl;
        }
    }
}

// ---------------- final combine ----------------
__global__ __launch_bounds__(256)
void combine_kernel(const float* __restrict__ h, const float* __restrict__ eo,
                    const int* __restrict__ slot01, const float* __restrict__ w01,
                    float* __restrict__ out){
    long long idx = blockIdx.x*256LL + threadIdx.x;
    if (idx >= (long long)NTOK*HDIM) return;
    int t = (int)(idx >> 11);
    int c = (int)(idx & 2047);
    float v = h[idx];
    v += w01[2*t]   * eo[(long long)slot01[2*t]  *HDIM + c];
    v += w01[2*t+1] * eo[(long long)slot01[2*t+1]*HDIM + c];
    out[idx] = v;
}

// ---------------- launch ----------------
extern "C" void kernel_launch(void* const* d_in, const int* in_sizes, int n_in,
                              void* d_out, int out_size){
    const float* hidden = (const float*)d_in[0];
    const int*   amask  = (const int*)  d_in[1];
    const int*   posids = (const int*)  d_in[2];
    const float* ln1w = (const float*)d_in[3];
    const float* ln1b = (const float*)d_in[4];
    const float* ln2w = (const float*)d_in[5];
    const float* ln2b = (const float*)d_in[6];
    const float* wq = (const float*)d_in[7];
    const float* bq = (const float*)d_in[8];
    const float* wk = (const float*)d_in[9];
    const float* bk = (const float*)d_in[10];
    const float* wv = (const float*)d_in[11];
    const float* bv = (const float*)d_in[12];
    const float* wo = (const float*)d_in[13];
    const float* bo = (const float*)d_in[14];
    const float* gatew = (const float*)d_in[15];
    const float* w1 = (const float*)d_in[16];
    const float* w2 = (const float*)d_in[17];
    const float* w3 = (const float*)d_in[18];
    float* out = (float*)d_out;

    __half *xln1h, *qkvh, *attnh, *xln2h, *acth;
    __half *wqh, *wkh, *wvh, *woh, *w1h, *w3h, *w2h;
    float *hbuf, *xln2, *eo, *w01, *bqkv;
    int *e01, *pos01, *counts, *offsets, *toklist, *slot01;
    cudaGetSymbolAddress((void**)&xln1h, g_xln1h);
    cudaGetSymbolAddress((void**)&qkvh, g_qkvh);
    cudaGetSymbolAddress((void**)&attnh, g_attnh);
    cudaGetSymbolAddress((void**)&hbuf, g_h);
    cudaGetSymbolAddress((void**)&xln2, g_xln2);
    cudaGetSymbolAddress((void**)&xln2h, g_xln2h);
    cudaGetSymbolAddress((void**)&acth, g_acth);
    cudaGetSymbolAddress((void**)&eo, g_eo);
    cudaGetSymbolAddress((void**)&wqh, g_wqh);
    cudaGetSymbolAddress((void**)&wkh, g_wkh);
    cudaGetSymbolAddress((void**)&wvh, g_wvh);
    cudaGetSymbolAddress((void**)&woh, g_woh);
    cudaGetSymbolAddress((void**)&w1h, g_w1h);
    cudaGetSymbolAddress((void**)&w3h, g_w3h);
    cudaGetSymbolAddress((void**)&w2h, g_w2h);
    cudaGetSymbolAddress((void**)&bqkv, g_bqkv);
    cudaGetSymbolAddress((void**)&e01, g_e01);
    cudaGetSymbolAddress((void**)&w01, g_w01);
    cudaGetSymbolAddress((void**)&pos01, g_pos01);
    cudaGetSymbolAddress((void**)&counts, g_counts);
    cudaGetSymbolAddress((void**)&offsets, g_offsets);
    cudaGetSymbolAddress((void**)&toklist, g_toklist);
    cudaGetSymbolAddress((void**)&slot01, g_slot01);

    cudaFuncSetAttribute(flash_kernel, cudaFuncAttributeMaxDynamicSharedMemorySize, FL_SMEM_BYTES);
    cudaFuncSetAttribute(gemm_f16,    cudaFuncAttributeMaxDynamicSharedMemorySize, GEMM_SMEM_BYTES);

    static cudaStream_t s2 = nullptr;
    static cudaEvent_t evFork = nullptr, evJoin = nullptr;
    if (!s2){
        cudaStreamCreateWithFlags(&s2, cudaStreamNonBlocking);
        cudaEventCreateWithFlags(&evFork, cudaEventDisableTiming);
        cudaEventCreateWithFlags(&evJoin, cudaEventDisableTiming);
    }

    auto cvt = [&](cudaStream_t st, const float* s, __half* d, long long n, int blocks){
        long long n8 = n >> 3;
        int nb = (int)((n8 + 255) / 256);
        if (nb > blocks) nb = blocks;
        cvt16<<<nb, 256, 0, st>>>((const float4*)s, (uint4*)d, n8);
    };

    // 0a) attention weights on main stream (full-size grids; they are quick)
    cvt(0, wq, wqh, (long long)HDIM*NHEAD*HEADD, 32768);
    cvt(0, wk, wkh, (long long)HDIM*NKVH*HEADD, 32768);
    cvt(0, wv, wvh, (long long)HDIM*NKVH*HEADD, 32768);
    cvt(0, wo, woh, (long long)HDIM*HDIM, 32768);
    concat_bias<<<(QKVN+255)/256, 256>>>(bq, bk, bv, bqkv);

    // 0b) fork: MoE conversion on side stream with LOW-FOOTPRINT persistent grids
    cudaEventRecord(evFork, 0);
    cudaStreamWaitEvent(s2, evFork, 0);
    cvt(s2, w1, w1h, (long long)NEXP*HDIM*FFN, 296);
    cvt(s2, w3, w3h, (long long)NEXP*HDIM*FFN, 296);
    cvt(s2, w2, w2h, (long long)NEXP*FFN*HDIM, 296);
    cudaEventRecord(evJoin, s2);

    // 1) LN1
    ln_kernel<<<NTOK, 256>>>(hidden, ln1w, ln1b, nullptr, xln1h);

    // 2) fused QKV projection
    {
        GemmSegs sg;
        sg.end[0] = NHEAD*HEADD; sg.end[1] = NHEAD*HEADD + NKVH*HEADD; sg.end[2] = QKVN;
        sg.B[0] = wqh; sg.B[1] = wkh; sg.B[2] = wvh;
        sg.ldb[0] = NHEAD*HEADD; sg.ldb[1] = NKVH*HEADD; sg.ldb[2] = NKVH*HEADD;
        gemm_f16<<<dim3(QKVN/256, NTOK/128, 1), 256, GEMM_SMEM_BYTES>>>(
            xln1h, HDIM, sg, 0, nullptr, qkvh, QKVN, bqkv, nullptr,
            NTOK, HDIM, 0, nullptr, nullptr, nullptr);
    }

    // 3) RoPE
    {
        int total = NTOK*(NHEAD+NKVH)*64;
        rope_kernel<<<(total+255)/256, 256>>>(qkvh, posids);
    }

    // 4) flash attention
    flash_kernel<<<dim3(SEQ/64, BATCH*NHEAD), 256, FL_SMEM_BYTES>>>(qkvh, amask, attnh);

    // 5) O projection + residual
    {
        GemmSegs sg;
        sg.end[0] = HDIM; sg.end[1] = HDIM; sg.end[2] = HDIM;
        sg.B[0] = woh; sg.B[1] = woh; sg.B[2] = woh;
        sg.ldb[0] = HDIM; sg.ldb[1] = HDIM; sg.ldb[2] = HDIM;
        gemm_f16<<<dim3(HDIM/256, NTOK/128, 1), 256, GEMM_SMEM_BYTES>>>(
            attnh, NHEAD*HEADD, sg, 0, hbuf, nullptr, HDIM, bo, hidden,
            NTOK, NHEAD*HEADD, 0, nullptr, nullptr, nullptr);
    }

    // 6) LN2
    ln_kernel<<<NTOK, 256>>>(hbuf, ln2w, ln2b, xln2, xln2h);
    // 7) gate + top2
    gate_kernel<<<NTOK, 256>>>(xln2, gatew, e01, w01);
    // 8) routing
    cudaMemsetAsync(counts, 0, NEXP*sizeof(int));
    route_count_kernel<<<(NTOK+255)/256, 256>>>(e01, counts, pos01);
    route_offset_kernel<<<1, 32>>>(counts, offsets);
    route_scatter_kernel<<<(NTOK+255)/256, 256>>>(e01, pos01, offsets, toklist, slot01);

    // join: MoE fp16 weights ready
    cudaStreamWaitEvent(0, evJoin, 0);

    // 9) fused up-projection + silu: act[slot][f] = silu(x@w1)[f] * (x@w3)[f]
    {
        GemmSegs sg;
        sg.end[0] = FFN; sg.end[1] = FFN; sg.end[2] = FFN;
        sg.B[0] = w1h; sg.B[1] = w3h; sg.B[2] = w3h;
        sg.ldb[0] = FFN; sg.ldb[1] = FFN; sg.ldb[2] = FFN;
        gemm_f16<<<dim3(FFN/128, NTOK/128, NEXP), 256, GEMM_SMEM_BYTES>>>(
            xln2h, HDIM, sg, (long long)HDIM*FFN, nullptr, acth, FFN, nullptr, nullptr,
            NTOK, HDIM, 1 /*paired*/, toklist, counts, offsets);
    }

    // 11) eo = act @ w2(e)
    {
        GemmSegs sg;
        sg.end[0] = HDIM; sg.end[1] = HDIM; sg.end[2] = HDIM;
        sg.B[0] = w2h; sg.B[1] = w2h; sg.B[2] = w2h;
        sg.ldb[0] = HDIM; sg.ldb[1] = HDIM; sg.ldb[2] = HDIM;
        gemm_f16<<<dim3(HDIM/256, NTOK/128, NEXP), 256, GEMM_SMEM_BYTES>>>(
            acth, FFN, sg, (long long)FFN*HDIM, eo, nullptr, HDIM, nullptr, nullptr,
            NTOK, FFN, 0, nullptr, counts, offsets);
    }

    // 12) combine
    combine_kernel<<<(int)(((long long)NTOK*HDIM + 255)/256), 256>>>(hbuf, eo, slot01, w01, out);
}

// round 13
// speedup vs baseline: 1.0052x; 1.0052x over previous
#include <cuda_runtime.h>
#include <cuda_fp16.h>
#include <math.h>
#include <stdint.h>

// ---------------- problem constants ----------------
#define BATCH 2
#define SEQ   1024
#define HDIM  2048
#define NHEAD 16
#define NKVH  4
#define HEADD 128
#define FFN   4096
#define NEXP  8
#define NTOK  (BATCH*SEQ)
#define QKVN  (NHEAD*HEADD + 2*NKVH*HEADD)   // 3072
#define NSLOT (2*NTOK)
#define LNEPS 1e-5f

// ---------------- device scratch ----------------
__device__ __half g_xln1h[NTOK*HDIM];
__device__ __half g_qkvh [NTOK*QKVN];
__device__ __half g_attnh[NTOK*NHEAD*HEADD];
__device__ float  g_h    [NTOK*HDIM];
__device__ float  g_xln2 [NTOK*HDIM];
__device__ __half g_xln2h[NTOK*HDIM];
__device__ __half g_acth [NSLOT*FFN];
__device__ float  g_eo   [NSLOT*HDIM];
// fp16 weights, ORIGINAL [K][N] layout
__device__ __half g_wqh [HDIM*NHEAD*HEADD];
__device__ __half g_wkh [HDIM*NKVH*HEADD];
__device__ __half g_wvh [HDIM*NKVH*HEADD];
__device__ __half g_woh [HDIM*HDIM];
__device__ __half g_w1h [NEXP*HDIM*FFN];
__device__ __half g_w3h [NEXP*HDIM*FFN];
__device__ __half g_w2h [NEXP*FFN*HDIM];
__device__ float  g_bqkv[QKVN];
// routing
__device__ int   g_e01 [NTOK*2];
__device__ float g_w01 [NTOK*2];
__device__ int   g_pos01[NTOK*2];
__device__ int   g_counts[NEXP];
__device__ int   g_offsets[NEXP];
__device__ int   g_toklist[NSLOT];
__device__ int   g_slot01[NTOK*2];

// ---------------- helpers ----------------
__device__ __forceinline__ void mma_f16(float* c, const uint32_t* a, const uint32_t* b){
    asm volatile(
      "mma.sync.aligned.m16n8k16.row.col.f32.f16.f16.f32 "
      "{%0,%1,%2,%3}, {%4,%5,%6,%7}, {%8,%9}, {%0,%1,%2,%3};\n"
      : "+f"(c[0]), "+f"(c[1]), "+f"(c[2]), "+f"(c[3])
      : "r"(a[0]), "r"(a[1]), "r"(a[2]), "r"(a[3]), "r"(b[0]), "r"(b[1]));
}
__device__ __forceinline__ void ldsm_x4(uint32_t& r0, uint32_t& r1, uint32_t& r2, uint32_t& r3,
                                        uint32_t addr){
    asm volatile("ldmatrix.sync.aligned.m8n8.x4.shared.b16 {%0,%1,%2,%3}, [%4];"
                 : "=r"(r0), "=r"(r1), "=r"(r2), "=r"(r3) : "r"(addr));
}
__device__ __forceinline__ void ldsm_x4_t(uint32_t& r0, uint32_t& r1, uint32_t& r2, uint32_t& r3,
                                          uint32_t addr){
    asm volatile("ldmatrix.sync.aligned.m8n8.x4.trans.shared.b16 {%0,%1,%2,%3}, [%4];"
                 : "=r"(r0), "=r"(r1), "=r"(r2), "=r"(r3) : "r"(addr));
}
__device__ __forceinline__ void cpa16h(__half* smem, const __half* gmem, bool pred){
    uint32_t s = (uint32_t)__cvta_generic_to_shared(smem);
    int sz = pred ? 16 : 0;
    asm volatile("cp.async.cg.shared.global [%0], [%1], 16, %2;\n"
                 :: "r"(s), "l"(gmem), "r"(sz));
}
#define CP_COMMIT() asm volatile("cp.async.commit_group;\n")
template<int N> __device__ __forceinline__ void cp_wait(){
    asm volatile("cp.async.wait_group %0;\n" :: "n"(N));
}

__device__ __forceinline__ float block_sum_256(float v){
    __shared__ float red[8];
    __shared__ float total;
    #pragma unroll
    for (int o = 16; o; o >>= 1) v += __shfl_xor_sync(0xffffffffu, v, o);
    if ((threadIdx.x & 31) == 0) red[threadIdx.x >> 5] = v;
    __syncthreads();
    if (threadIdx.x == 0){
        float s = 0.f;
        #pragma unroll
        for (int i = 0; i < 8; i++) s += red[i];
        total = s;
    }
    __syncthreads();
    float r = total;
    __syncthreads();
    return r;
}

// ---------------- streaming fp32 -> fp16 convert ----------------
__global__ __launch_bounds__(256)
void cvt16(const float4* __restrict__ src, uint4* __restrict__ dst, long long n8){
    for (long long i = blockIdx.x*256LL + threadIdx.x; i < n8; i += gridDim.x*256LL){
        float4 v0 = src[2*i], v1 = src[2*i+1];
        __half2 a = __floats2half2_rn(v0.x, v0.y);
        __half2 b = __floats2half2_rn(v0.z, v0.w);
        __half2 c = __floats2half2_rn(v1.x, v1.y);
        __half2 d = __floats2half2_rn(v1.z, v1.w);
        uint4 o;
        o.x = *(uint32_t*)&a; o.y = *(uint32_t*)&b;
        o.z = *(uint32_t*)&c; o.w = *(uint32_t*)&d;
        dst[i] = o;
    }
}

__global__ void concat_bias(const float* bq, const float* bk, const float* bv, float* dst){
    int i = blockIdx.x*256 + threadIdx.x;
    if (i < NHEAD*HEADD) dst[i] = bq[i];
    else if (i < NHEAD*HEADD + NKVH*HEADD) dst[i] = bk[i - NHEAD*HEADD];
    else if (i < QKVN) dst[i] = bv[i - NHEAD*HEADD - NKVH*HEADD];
}

// ---------------- LayerNorm ----------------
__global__ __launch_bounds__(256)
void ln_kernel(const float* __restrict__ x, const float* __restrict__ w,
               const float* __restrict__ b,
               float* __restrict__ yraw, __half* __restrict__ yh){
    long long row = blockIdx.x;
    const float* xr = x + row * HDIM;
    float v[8]; float s = 0.f;
    #pragma unroll
    for (int i = 0; i < 8; i++){ v[i] = xr[threadIdx.x + 256*i]; s += v[i]; }
    float mean = block_sum_256(s) * (1.f/HDIM);
    float ss = 0.f;
    #pragma unroll
    for (int i = 0; i < 8; i++){ float d = v[i]-mean; ss += d*d; }
    float var = block_sum_256(ss) * (1.f/HDIM);
    float rstd = rsqrtf(var + LNEPS);
    #pragma unroll
    for (int i = 0; i < 8; i++){
        int c = threadIdx.x + 256*i;
        float o = (v[i]-mean)*rstd*w[c] + b[c];
        if (yraw) yraw[row*HDIM + c] = o;
        yh[row*HDIM + c] = __float2half(o);
    }
}

// ---------------- fp16 GEMM: ldmatrix A + ldmatrix.trans B ----------------
// paired mode: each CTA computes 128 cols of B0 (h1) + matching 128 cols of B1 (h3),
// and writes act = silu(h1)*h3 (fp16) via smem exchange in the epilogue.
struct GemmSegs {
    int end[3];
    const __half* B[3];
    int ldb[3];
};

#define GA_STG (128*40)
#define GB_STG (32*264)
#define GB_BASE (3*GA_STG)
#define GEMM_SMEM_BYTES ((GB_BASE + 3*GB_STG)*2)   // 81408 >= 64KB exch

__global__ __launch_bounds__(256)
void gemm_f16(const __half* __restrict__ A, int lda,
              GemmSegs segs, long long bStride,
              float* __restrict__ Cf, __half* __restrict__ Ch, int ldc,
              const float* __restrict__ bias, const float* __restrict__ resid,
              int M, int K, int paired,
              const int* __restrict__ rowidx,
              const int* __restrict__ counts,
              const int* __restrict__ offsets)
{
    extern __shared__ __half hsm[];
#define ASH(st, r, c) hsm[(st)*GA_STG + (r)*40 + (c)]
#define BSH(st, k, c) hsm[GB_BASE + (st)*GB_STG + (k)*264 + (c)]

    int e = blockIdx.z;
    int rowStart = 0, Mm = M;
    if (counts){ Mm = counts[e]; rowStart = offsets[e]; }
    int mbase = blockIdx.y * 128;
    if (mbase >= Mm) return;

    int tid  = threadIdx.x;
    int lane = tid & 31, wid = tid >> 5;
    int warpM = wid >> 2, warpN = wid & 3;
    int g = lane >> 2, t4 = lane & 3;
    int brow = tid >> 3, bch = tid & 7;

    int nbase = 0, ldb;
    const __half* bptr[4];
    if (paired){
        int nb = blockIdx.x * 128;
        ldb = segs.ldb[0];
        const __half* B0p = segs.B[0] + (long long)e*bStride + nb;
        const __half* B1p = segs.B[1] + (long long)e*bStride + nb;
        #pragma unroll
        for (int i = 0; i < 4; i++){
            int c8 = (bch + 8*i)*8;
            bptr[i] = (c8 < 128) ? (B0p + c8) : (B1p + c8 - 128);
        }
    } else {
        nbase = blockIdx.x * 256;
        int s = 0;
        if (nbase >= segs.end[0]) s = 1;
        if (nbase >= segs.end[1]) s = 2;
        int segStart = (s == 0) ? 0 : segs.end[s-1];
        ldb = segs.ldb[s];
        const __half* Bp = segs.B[s] + (long long)e*bStride + (nbase - segStart);
        #pragma unroll
        for (int i = 0; i < 4; i++)
            bptr[i] = Bp + (bch + 8*i)*8;
    }

    int ar = tid >> 1, hsel = tid & 1;
    bool aval = (mbase + ar < Mm);
    int arow = 0;
    if (aval) arow = rowidx ? rowidx[rowStart + mbase + ar] : (rowStart + mbase + ar);
    const __half* aptr = A + (long long)arow * lda + hsel*16;

    uint32_t smbase = (uint32_t)__cvta_generic_to_shared(hsm);
    int a_m = (lane & 7) + 8*((lane >> 3) & 1);
    int a_k = 8*((lane >> 4) & 1);
    uint32_t asm0 = smbase + (uint32_t)((warpM*64 + a_m)*40 + a_k)*2;
    int k_off = (lane & 7) + 8*((lane >> 3) & 1);
    int c_off = warpN*64 + 8*((lane >> 4) & 1);
    uint32_t bsm0 = smbase + GB_BASE*2 + (uint32_t)(k_off*264 + c_off)*2;

    float acc[32][4];
    #pragma unroll
    for (int i = 0; i < 32; i++)
        #pragma unroll
        for (int j = 0; j < 4; j++) acc[i][j] = 0.f;

    int nk = K >> 5;

#define GEMM_ISSUE(KT, ST) do {                                               \
        cpa16h(&ASH(ST, ar, hsel*16),     aptr + (KT)*32,     aval);          \
        cpa16h(&ASH(ST, ar, hsel*16 + 8), aptr + (KT)*32 + 8, aval);          \
        _Pragma("unroll")                                                     \
        for (int i = 0; i < 4; i++){                                          \
            int c8 = (bch + 8*i)*8;                                           \
            cpa16h(&BSH(ST, brow, c8),                                        \
                   bptr[i] + (long long)((KT)*32 + brow)*ldb, true);          \
        }                                                                     \
    } while(0)

    GEMM_ISSUE(0, 0); CP_COMMIT();
    GEMM_ISSUE(1, 1); CP_COMMIT();

    int cur = 0;
    for (int kt = 0; kt < nk; ++kt){
        if (kt + 1 < nk) cp_wait<1>(); else cp_wait<0>();
        __syncthreads();
        if (kt + 2 < nk){
            int nxt = cur + 2; if (nxt >= 3) nxt -= 3;
            GEMM_ISSUE(kt+2, nxt); CP_COMMIT();
        }

        #pragma unroll
        for (int ks = 0; ks < 2; ++ks){
            uint32_t af[4][4], bf[8][2];
            uint32_t aadr = asm0 + (uint32_t)cur*(GA_STG*2) + (uint32_t)(ks*16*2);
            #pragma unroll
            for (int ma = 0; ma < 4; ma++){
                ldsm_x4(af[ma][0], af[ma][1], af[ma][2], af[ma][3],
                        aadr + (uint32_t)(ma*16*40*2));
            }
            uint32_t badr = bsm0 + (uint32_t)cur*(GB_STG*2) + (uint32_t)(ks*16*264*2);
            #pragma unroll
            for (int p = 0; p < 4; p++){
                ldsm_x4_t(bf[2*p][0], bf[2*p][1], bf[2*p+1][0], bf[2*p+1][1],
                          badr + (uint32_t)(p*16*2));
            }
            #pragma unroll
            for (int ma = 0; ma < 4; ma++)
                #pragma unroll
                for (int na = 0; na < 8; na++)
                    mma_f16(acc[ma*8+na], af[ma], bf[na]);
        }
        cur = cur + 1; if (cur >= 3) cur -= 3;
    }

    if (!paired){
        #pragma unroll
        for (int ma = 0; ma < 4; ma++){
            #pragma unroll
            for (int na = 0; na < 8; na++){
                float* a4 = acc[ma*8+na];
                #pragma unroll
                for (int half_ = 0; half_ < 2; half_++){
                    int lrow = warpM*64 + ma*16 + g + (half_ ? 8 : 0);
                    int gcol = nbase + warpN*64 + na*8 + 2*t4;
                    int gr = mbase + lrow;
                    if (gr < Mm){
                        long long orow = rowStart + gr;
                        float v0 = a4[half_*2+0];
                        float v1 = a4[half_*2+1];
                        if (bias){ v0 += bias[gcol]; v1 += bias[gcol+1]; }
                        if (resid){
                            const float* rp = &resid[orow*(long long)ldc + gcol];
                            v0 += rp[0]; v1 += rp[1];
                        }
                        if (Cf){
                            *(float2*)&Cf[orow*(long long)ldc + gcol] = make_float2(v0, v1);
                        } else {
                            *(__half2*)&Ch[orow*(long long)ldc + gcol] = __floats2half2_rn(v0, v1);
                        }
                    }
                }
            }
        }
    } else {
        __syncthreads();
        float* exch = (float*)hsm; // 128 x 128 floats = 64 KB
        int isH3 = warpN >> 1;
        int colBase = (warpN & 1)*64;
        if (isH3){
            #pragma unroll
            for (int ma = 0; ma < 4; ma++)
                #pragma unroll
                for (int na = 0; na < 8; na++){
                    float* a4 = acc[ma*8+na];
                    #pragma unroll
                    for (int half_ = 0; half_ < 2; half_++){
                        int lrow = warpM*64 + ma*16 + g + (half_ ? 8 : 0);
                        int lcol = colBase + na*8 + 2*t4;
                        exch[lrow*128 + lcol    ] = a4[half_*2+0];
                        exch[lrow*128 + lcol + 1] = a4[half_*2+1];
                    }
                }
        }
        __syncthreads();
        if (!isH3){
            int nb = blockIdx.x * 128;
            #pragma unroll
            for (int ma = 0; ma < 4; ma++)
                #pragma unroll
                for (int na = 0; na < 8; na++){
                    float* a4 = acc[ma*8+na];
                    #pragma unroll
                    for (int half_ = 0; half_ < 2; half_++){
                        int lrow = warpM*64 + ma*16 + g + (half_ ? 8 : 0);
                        int lcol = colBase + na*8 + 2*t4;
                        int gr = mbase + lrow;
                        if (gr < Mm){
                            long long orow = rowStart + gr;
                            float v0 = a4[half_*2+0];
                            float v1 = a4[half_*2+1];
                            float u0 = exch[lrow*128 + lcol    ];
                            float u1 = exch[lrow*128 + lcol + 1];
                            float r0 = v0 / (1.f + expf(-v0)) * u0;
                            float r1 = v1 / (1.f + expf(-v1)) * u1;
                            *(__half2*)&Ch[orow*(long long)ldc + nb + lcol] =
                                __floats2half2_rn(r0, r1);
                        }
                    }
                }
        }
    }
#undef ASH
#undef BSH
#undef GEMM_ISSUE
}

// ---------------- RoPE ----------------
__global__ __launch_bounds__(256)
void rope_kernel(__half* __restrict__ qkv, const int* __restrict__ pos_ids){
    int idx = blockIdx.x*256 + threadIdx.x;
    const int total = NTOK*(NHEAD+NKVH)*64;
    if (idx >= total) return;
    int j    = idx & 63;
    int rest = idx >> 6;
    int head = rest % (NHEAD+NKVH);
    int t    = rest / (NHEAD+NKVH);
    __half* p;
    if (head < NHEAD) p = qkv + (long long)t*QKVN + head*HEADD;
    else              p = qkv + (long long)t*QKVN + NHEAD*HEADD + (head-NHEAD)*HEADD;
    double inv = exp((double)j * -0.21586735246819178);
    float th = (float)pos_ids[t] * (float)inv;
    float sn, cs; sincosf(th, &sn, &cs);
    float x0 = __half2float(p[j]), x1 = __half2float(p[j+64]);
    p[j]    = __float2half(x0*cs - x1*sn);
    p[j+64] = __float2half(x1*cs + x0*sn);
}

// ---------------- fp16 tensor-core flash attention ----------------
#define FKT 32
#define FL_PS_F   (64*36)
#define FL_FLOATS (FL_PS_F + 64*3 + 32)
#define FL_QS_H   0
#define FL_KS_H   (FL_QS_H + 64*136)
#define FL_VS_H   (FL_KS_H + FKT*136)
#define FL_PH_H   (FL_VS_H + FKT*136)
#define FL_HALVES (FL_PH_H + 64*40)
#define FL_SMEM_BYTES (FL_FLOATS*4 + FL_HALVES*2)

__global__ __launch_bounds__(256, 2)
void flash_kernel(const __half* __restrict__ qkv, const int* __restrict__ amask,
                  __half* __restrict__ O)
{
    extern __shared__ float sm[];
    float* Ps   = sm;
    float* mrow = sm + FL_PS_F;
    float* lrow = mrow + 64;
    float* srow = lrow + 64;
    int*   mk   = (int*)(srow + 64);
    __half* hb  = (__half*)(sm + FL_FLOATS);
    __half* Qs = hb + FL_QS_H;
    __half* Ks = hb + FL_KS_H;
    __half* Vs = hb + FL_VS_H;
    __half* Ph = hb + FL_PH_H;

    int qt = blockIdx.x;
    int bh = blockIdx.y;
    int b  = bh >> 4, h = bh & 15;
    int kvh = h >> 2;
    int tid = threadIdx.x;
    int lane = tid & 31, wid = tid >> 5;
    int g = lane >> 2, t4 = lane & 3;
    int mS = wid & 3;
    int nH = wid >> 2;

    int vk = (lane & 7) + 8*((lane >> 3) & 1);
    int vc = 8*((lane >> 4) & 1);
    uint32_t vbase = (uint32_t)__cvta_generic_to_shared(Vs) + (uint32_t)(vk*136 + 64*nH + vc)*2;

    for (int e2 = tid; e2 < 64*64; e2 += 256){
        int row = e2 >> 6; int d2 = (e2 & 63)*2;
        *(uint32_t*)&Qs[row*136 + d2] =
            *(const uint32_t*)&qkv[(long long)(b*SEQ + qt*64 + row)*QKVN + h*HEADD + d2];
    }
    if (tid < 64){ mrow[tid] = -1e30f; lrow[tid] = 0.f; }

    float oacc[8][4];
    #pragma unroll
    for (int i = 0; i < 8; i++)
        #pragma unroll
        for (int j = 0; j < 4; j++) oacc[i][j] = 0.f;

    const float iscale = 0.08838834764831843f;

    int nkt = 2*qt + 2;
    for (int kt = 0; kt < nkt; ++kt){
        __syncthreads();
        for (int e2 = tid; e2 < FKT*64; e2 += 256){
            int kk = e2 >> 6; int d2 = (e2 & 63)*2;
            long long base = (long long)(b*SEQ + kt*FKT + kk)*QKVN + NHEAD*HEADD + kvh*HEADD;
            *(uint32_t*)&Ks[kk*136 + d2] = *(const uint32_t*)&qkv[base + d2];
            *(uint32_t*)&Vs[kk*136 + d2] = *(const uint32_t*)&qkv[base + NKVH*HEADD + d2];
        }
        if (tid < FKT) mk[tid] = amask[b*SEQ + kt*FKT + tid];
        __syncthreads();

        float sacc[2][4];
        #pragma unroll
        for (int i = 0; i < 2; i++)
            #pragma unroll
            for (int j = 0; j < 4; j++) sacc[i][j] = 0.f;
        #pragma unroll
        for (int ks = 0; ks < 8; ++ks){
            int k0 = ks*16;
            uint32_t a[4];
            int r = 16*mS;
            a[0] = *(const uint32_t*)&Qs[(r+g  )*136 + k0 + 2*t4    ];
            a[1] = *(const uint32_t*)&Qs[(r+g+8)*136 + k0 + 2*t4    ];
            a[2] = *(const uint32_t*)&Qs[(r+g  )*136 + k0 + 2*t4 + 8];
            a[3] = *(const uint32_t*)&Qs[(r+g+8)*136 + k0 + 2*t4 + 8];
            #pragma unroll
            for (int j = 0; j < 2; j++){
                int c = 16*nH + 8*j + g;
                uint32_t bfr[2];
                bfr[0] = *(const uint32_t*)&Ks[c*136 + k0 + 2*t4    ];
                bfr[1] = *(const uint32_t*)&Ks[c*136 + k0 + 2*t4 + 8];
                mma_f16(sacc[j], a, bfr);
            }
        }
        #pragma unroll
        for (int j = 0; j < 2; j++){
            #pragma unroll
            for (int cr = 0; cr < 4; cr++){
                int row = 16*mS + g + ((cr >= 2) ? 8 : 0);
                int col = 16*nH + 8*j + 2*t4 + (cr & 1);
                int sq = qt*64 + row, sk = kt*FKT + col;
                float vv = sacc[j][cr]*iscale;
                if (sk > sq || mk[col] == 0) vv = -1e30f;
                Ps[row*36 + col] = vv;
            }
        }
        __syncthreads();

        if (tid < 64){
            int r = tid;
            float mo = mrow[r], mx = mo;
            #pragma unroll 8
            for (int kk = 0; kk < FKT; kk++) mx = fmaxf(mx, Ps[r*36+kk]);
            float sc = __expf(mo - mx);
            float ssum = 0.f;
            #pragma unroll 8
            for (int kk = 0; kk < FKT; kk++){
                float p = __expf(Ps[r*36+kk] - mx);
                ssum += p;
                Ph[r*40+kk] = __float2half(p);
            }
            lrow[r] = lrow[r]*sc + ssum;
            mrow[r] = mx;
            srow[r] = sc;
        }
        __syncthreads();

        {
            float sc0 = srow[16*mS + g];
            float sc1 = srow[16*mS + g + 8];
            #pragma unroll
            for (int j = 0; j < 8; j++){
                oacc[j][0] *= sc0; oacc[j][1] *= sc0;
                oacc[j][2] *= sc1; oacc[j][3] *= sc1;
            }
        }
        #pragma unroll
        for (int ks = 0; ks < 2; ++ks){
            int k0 = ks*16 + 2*t4;
            uint32_t a[4];
            int r = 16*mS;
            a[0] = *(const uint32_t*)&Ph[(r+g  )*40 + k0    ];
            a[1] = *(const uint32_t*)&Ph[(r+g+8)*40 + k0    ];
            a[2] = *(const uint32_t*)&Ph[(r+g  )*40 + k0 + 8];
            a[3] = *(const uint32_t*)&Ph[(r+g+8)*40 + k0 + 8];
            uint32_t badr = vbase + (uint32_t)(ks*16*136*2);
            uint32_t bf[8][2];
            #pragma unroll
            for (int p = 0; p < 4; p++){
                ldsm_x4_t(bf[2*p][0], bf[2*p][1], bf[2*p+1][0], bf[2*p+1][1],
                          badr + (uint32_t)(p*16*2));
            }
            #pragma unroll
            for (int j = 0; j < 8; j++)
                mma_f16(oacc[j], a, bf[j]);
        }
    }

    #pragma unroll
    for (int j = 0; j < 8; j++){
        #pragma unroll
        for (int half_ = 0; half_ < 2; half_++){
            int row = 16*mS + g + (half_ ? 8 : 0);
            int col = 64*nH + 8*j + 2*t4;
            int sq = qt*64 + row;
            float inv = 1.f / lrow[row];
            __half2 o2 = __floats2half2_rn(oacc[j][half_*2+0]*inv, oacc[j][half_*2+1]*inv);
            *(__half2*)&O[(((long long)(b*SEQ + sq))*NHEAD + h)*HEADD + col] = o2;
        }
    }
}

// ---------------- gate + top2 (raw fp32) ----------------
__global__ __launch_bounds__(256)
void gate_kernel(const float* __restrict__ x2, const float* __restrict__ gw,
                 int* __restrict__ e01, float* __restrict__ w01){
    long long t = blockIdx.x;
    const float* xr = x2 + t*HDIM;
    float part[NEXP];
    #pragma unroll
    for (int e = 0; e < NEXP; e++) part[e] = 0.f;
    for (int hh = threadIdx.x; hh < HDIM; hh += 256){
        float xv = xr[hh];
        const float* gp = gw + (long long)hh*NEXP;
        #pragma unroll
        for (int e = 0; e < NEXP; e++) part[e] += xv*gp[e];
    }
    __shared__ float red[8][NEXP];
    #pragma unroll
    for (int e = 0; e < NEXP; e++){
        float v = part[e];
        #pragma unroll
        for (int o = 16; o; o >>= 1) v += __shfl_xor_sync(0xffffffffu, v, o);
        if ((threadIdx.x & 31) == 0) red[threadIdx.x >> 5][e] = v;
    }
    __syncthreads();
    if (threadIdx.x == 0){
        float lg[NEXP];
        #pragma unroll
        for (int e = 0; e < NEXP; e++){
            float s = 0.f;
            #pragma unroll
            for (int w8 = 0; w8 < 8; w8++) s += red[w8][e];
            lg[e] = s;
        }
        int b0 = 0;
        #pragma unroll
        for (int e = 1; e < NEXP; e++) if (lg[e] > lg[b0]) b0 = e;
        int b1 = -1;
        #pragma unroll
        for (int e = 0; e < NEXP; e++)
            if (e != b0 && (b1 < 0 || lg[e] > lg[b1])) b1 = e;
        float t0 = 1.f / (1.f + expf(lg[b1] - lg[b0]));
        e01[2*t] = b0; e01[2*t+1] = b1;
        w01[2*t] = t0; w01[2*t+1] = 1.f - t0;
    }
}

// ---------------- routing ----------------
__global__ void route_count_kernel(const int* __restrict__ e01,
                                   int* __restrict__ counts, int* __restrict__ pos01){
    int t = blockIdx.x*blockDim.x + threadIdx.x;
    if (t < NTOK){
        pos01[2*t]   = atomicAdd(&counts[e01[2*t]],   1);
        pos01[2*t+1] = atomicAdd(&counts[e01[2*t+1]], 1);
    }
}
__global__ void route_offset_kernel(const int* __restrict__ counts, int* __restrict__ offsets){
    if (threadIdx.x == 0 && blockIdx.x == 0){
        int s = 0;
        for (int e = 0; e < NEXP; e++){ offsets[e] = s; s += counts[e]; }
    }
}
__global__ void route_scatter_kernel(const int* __restrict__ e01, const int* __restrict__ pos01,
                                     const int* __restrict__ offsets,
                                     int* __restrict__ toklist, int* __restrict__ slot01){
    int t = blockIdx.x*blockDim.x + threadIdx.x;
    if (t < NTOK){
        #pragma unroll
        for (int j = 0; j < 2; j++){
            int sl = offsets[e01[2*t+j]] + pos01[2*t+j];
            toklist[sl] = t;
            slot01[2*t+j] = sl;
        }
    }
}

// ---------------- final combine ----------------
__global__ __launch_bounds__(256)
void combine_kernel(const float* __restrict__ h, const float* __restrict__ eo,
                    const int* __restrict__ slot01, const float* __restrict__ w01,
                    float* __restrict__ out){
    long long idx = blockIdx.x*256LL + threadIdx.x;
    if (idx >= (long long)NTOK*HDIM) return;
    int t = (int)(idx >> 11);
    int c = (int)(idx & 2047);
    float v = h[idx];
    v += w01[2*t]   * eo[(long long)slot01[2*t]  *HDIM + c];
    v += w01[2*t+1] * eo[(long long)slot01[2*t+1]*HDIM + c];
    out[idx] = v;
}

// ---------------- launch ----------------
extern "C" void kernel_launch(void* const* d_in, const int* in_sizes, int n_in,
                              void* d_out, int out_size){
    const float* hidden = (const float*)d_in[0];
    const int*   amask  = (const int*)  d_in[1];
    const int*   posids = (const int*)  d_in[2];
    const float* ln1w = (const float*)d_in[3];
    const float* ln1b = (const float*)d_in[4];
    const float* ln2w = (const float*)d_in[5];
    const float* ln2b = (const float*)d_in[6];
    const float* wq = (const float*)d_in[7];
    const float* bq = (const float*)d_in[8];
    const float* wk = (const float*)d_in[9];
    const float* bk = (const float*)d_in[10];
    const float* wv = (const float*)d_in[11];
    const float* bv = (const float*)d_in[12];
    const float* wo = (const float*)d_in[13];
    const float* bo = (const float*)d_in[14];
    const float* gatew = (const float*)d_in[15];
    const float* w1 = (const float*)d_in[16];
    const float* w2 = (const float*)d_in[17];
    const float* w3 = (const float*)d_in[18];
    float* out = (float*)d_out;

    __half *xln1h, *qkvh, *attnh, *xln2h, *acth;
    __half *wqh, *wkh, *wvh, *woh, *w1h, *w3h, *w2h;
    float *hbuf, *xln2, *eo, *w01, *bqkv;
    int *e01, *pos01, *counts, *offsets, *toklist, *slot01;
    cudaGetSymbolAddress((void**)&xln1h, g_xln1h);
    cudaGetSymbolAddress((void**)&qkvh, g_qkvh);
    cudaGetSymbolAddress((void**)&attnh, g_attnh);
    cudaGetSymbolAddress((void**)&hbuf, g_h);
    cudaGetSymbolAddress((void**)&xln2, g_xln2);
    cudaGetSymbolAddress((void**)&xln2h, g_xln2h);
    cudaGetSymbolAddress((void**)&acth, g_acth);
    cudaGetSymbolAddress((void**)&eo, g_eo);
    cudaGetSymbolAddress((void**)&wqh, g_wqh);
    cudaGetSymbolAddress((void**)&wkh, g_wkh);
    cudaGetSymbolAddress((void**)&wvh, g_wvh);
    cudaGetSymbolAddress((void**)&woh, g_woh);
    cudaGetSymbolAddress((void**)&w1h, g_w1h);
    cudaGetSymbolAddress((void**)&w3h, g_w3h);
    cudaGetSymbolAddress((void**)&w2h, g_w2h);
    cudaGetSymbolAddress((void**)&bqkv, g_bqkv);
    cudaGetSymbolAddress((void**)&e01, g_e01);
    cudaGetSymbolAddress((void**)&w01, g_w01);
    cudaGetSymbolAddress((void**)&pos01, g_pos01);
    cudaGetSymbolAddress((void**)&counts, g_counts);
    cudaGetSymbolAddress((void**)&offsets, g_offsets);
    cudaGetSymbolAddress((void**)&toklist, g_toklist);
    cudaGetSymbolAddress((void**)&slot01, g_slot01);

    cudaFuncSetAttribute(flash_kernel, cudaFuncAttributeMaxDynamicSharedMemorySize, FL_SMEM_BYTES);
    cudaFuncSetAttribute(gemm_f16,    cudaFuncAttributeMaxDynamicSharedMemorySize, GEMM_SMEM_BYTES);

    static cudaStream_t s2 = nullptr;
    static cudaEvent_t evFork = nullptr, evJoin = nullptr;
    if (!s2){
        cudaStreamCreateWithFlags(&s2, cudaStreamNonBlocking);
        cudaEventCreateWithFlags(&evFork, cudaEventDisableTiming);
        cudaEventCreateWithFlags(&evJoin, cudaEventDisableTiming);
    }

    auto cvt = [&](cudaStream_t st, const float* s, __half* d, long long n){
        long long n8 = n >> 3;
        int nb = (int)((n8 + 255) / 256);
        if (nb > 32768) nb = 32768;
        cvt16<<<nb, 256, 0, st>>>((const float4*)s, (uint4*)d, n8);
    };

    // 0a) attention weights on main stream
    cvt(0, wq, wqh, (long long)HDIM*NHEAD*HEADD);
    cvt(0, wk, wkh, (long long)HDIM*NKVH*HEADD);
    cvt(0, wv, wvh, (long long)HDIM*NKVH*HEADD);
    cvt(0, wo, woh, (long long)HDIM*HDIM);
    concat_bias<<<(QKVN+255)/256, 256>>>(bq, bk, bv, bqkv);

    // 0b) fork: MoE conversion on side stream (full-size grids — R10 config)
    cudaEventRecord(evFork, 0);
    cudaStreamWaitEvent(s2, evFork, 0);
    cvt(s2, w1, w1h, (long long)NEXP*HDIM*FFN);
    cvt(s2, w3, w3h, (long long)NEXP*HDIM*FFN);
    cvt(s2, w2, w2h, (long long)NEXP*FFN*HDIM);
    cudaEventRecord(evJoin, s2);

    // 1) LN1
    ln_kernel<<<NTOK, 256>>>(hidden, ln1w, ln1b, nullptr, xln1h);

    // 2) fused QKV projection
    {
        GemmSegs sg;
        sg.end[0] = NHEAD*HEADD; sg.end[1] = NHEAD*HEADD + NKVH*HEADD; sg.end[2] = QKVN;
        sg.B[0] = wqh; sg.B[1] = wkh; sg.B[2] = wvh;
        sg.ldb[0] = NHEAD*HEADD; sg.ldb[1] = NKVH*HEADD; sg.ldb[2] = NKVH*HEADD;
        gemm_f16<<<dim3(QKVN/256, NTOK/128, 1), 256, GEMM_SMEM_BYTES>>>(
            xln1h, HDIM, sg, 0, nullptr, qkvh, QKVN, bqkv, nullptr,
            NTOK, HDIM, 0, nullptr, nullptr, nullptr);
    }

    // 3) RoPE
    {
        int total = NTOK*(NHEAD+NKVH)*64;
        rope_kernel<<<(total+255)/256, 256>>>(qkvh, posids);
    }

    // 4) flash attention
    flash_kernel<<<dim3(SEQ/64, BATCH*NHEAD), 256, FL_SMEM_BYTES>>>(qkvh, amask, attnh);

    // 5) O projection + residual
    {
        GemmSegs sg;
        sg.end[0] = HDIM; sg.end[1] = HDIM; sg.end[2] = HDIM;
        sg.B[0] = woh; sg.B[1] = woh; sg.B[2] = woh;
        sg.ldb[0] = HDIM; sg.ldb[1] = HDIM; sg.ldb[2] = HDIM;
        gemm_f16<<<dim3(HDIM/256, NTOK/128, 1), 256, GEMM_SMEM_BYTES>>>(
            attnh, NHEAD*HEADD, sg, 0, hbuf, nullptr, HDIM, bo, hidden,
            NTOK, NHEAD*HEADD, 0, nullptr, nullptr, nullptr);
    }

    // 6) LN2
    ln_kernel<<<NTOK, 256>>>(hbuf, ln2w, ln2b, xln2, xln2h);
    // 7) gate + top2
    gate_kernel<<<NTOK, 256>>>(xln2, gatew, e01, w01);
    // 8) routing
    cudaMemsetAsync(counts, 0, NEXP*sizeof(int));
    route_count_kernel<<<(NTOK+255)/256, 256>>>(e01, counts, pos01);
    route_offset_kernel<<<1, 32>>>(counts, offsets);
    route_scatter_kernel<<<(NTOK+255)/256, 256>>>(e01, pos01, offsets, toklist, slot01);

    // join: MoE fp16 weights ready
    cudaStreamWaitEvent(0, evJoin, 0);

    // 9) fused up-projection + silu: act[slot][f] = silu(x@w1)[f] * (x@w3)[f]
    {
        GemmSegs sg;
        sg.end[0] = FFN; sg.end[1] = FFN; sg.end[2] = FFN;
        sg.B[0] = w1h; sg.B[1] = w3h; sg.B[2] = w3h;
        sg.ldb[0] = FFN; sg.ldb[1] = FFN; sg.ldb[2] = FFN;
        gemm_f16<<<dim3(FFN/128, NTOK/128, NEXP), 256, GEMM_SMEM_BYTES>>>(
            xln2h, HDIM, sg, (long long)HDIM*FFN, nullptr, acth, FFN, nullptr, nullptr,
            NTOK, HDIM, 1 /*paired*/, toklist, counts, offsets);
    }

    // 11) eo = act @ w2(e)
    {
        GemmSegs sg;
        sg.end[0] = HDIM; sg.end[1] = HDIM; sg.end[2] = HDIM;
        sg.B[0] = w2h; sg.B[1] = w2h; sg.B[2] = w2h;
        sg.ldb[0] = HDIM; sg.ldb[1] = HDIM; sg.ldb[2] = HDIM;
        gemm_f16<<<dim3(HDIM/256, NTOK/128, NEXP), 256, GEMM_SMEM_BYTES>>>(
            acth, FFN, sg, (long long)FFN*HDIM, eo, nullptr, HDIM, nullptr, nullptr,
            NTOK, FFN, 0, nullptr, counts, offsets);
    }

    // 12) combine
    combine_kernel<<<(int)(((long long)NTOK*HDIM + 255)/256), 256>>>(hbuf, eo, slot01, w01, out);
}

// round 14
// speedup vs baseline: 1.0225x; 1.0172x over previous
#include <cuda_runtime.h>
#include <cuda_fp16.h>
#include <math.h>
#include <stdint.h>

// ---------------- problem constants ----------------
#define BATCH 2
#define SEQ   1024
#define HDIM  2048
#define NHEAD 16
#define NKVH  4
#define HEADD 128
#define FFN   4096
#define NEXP  8
#define NTOK  (BATCH*SEQ)
#define QKVN  (NHEAD*HEADD + 2*NKVH*HEADD)   // 3072
#define NSLOT (2*NTOK)
#define LNEPS 1e-5f

// ---------------- device scratch ----------------
__device__ __half g_xln1h[NTOK*HDIM];
__device__ __half g_qkvh [NTOK*QKVN];
__device__ __half g_attnh[NTOK*NHEAD*HEADD];
__device__ float  g_h    [NTOK*HDIM];
__device__ float  g_xln2 [NTOK*HDIM];
__device__ __half g_xln2h[NTOK*HDIM];
__device__ __half g_h13h [NSLOT*2*FFN];
__device__ __half g_acth [NSLOT*FFN];
__device__ float  g_eo   [NSLOT*HDIM];
// fp16 weights, ORIGINAL [K][N] layout
__device__ __half g_wqh [HDIM*NHEAD*HEADD];
__device__ __half g_wkh [HDIM*NKVH*HEADD];
__device__ __half g_wvh [HDIM*NKVH*HEADD];
__device__ __half g_woh [HDIM*HDIM];
__device__ __half g_w1h [NEXP*HDIM*FFN];
__device__ __half g_w3h [NEXP*HDIM*FFN];
__device__ __half g_w2h [NEXP*FFN*HDIM];
__device__ float  g_bqkv[QKVN];
// routing
__device__ int   g_e01 [NTOK*2];
__device__ float g_w01 [NTOK*2];
__device__ int   g_pos01[NTOK*2];
__device__ int   g_counts[NEXP];
__device__ int   g_offsets[NEXP];
__device__ int   g_toklist[NSLOT];
__device__ int   g_slot01[NTOK*2];

// ---------------- helpers ----------------
__device__ __forceinline__ void mma_f16(float* c, const uint32_t* a, const uint32_t* b){
    asm volatile(
      "mma.sync.aligned.m16n8k16.row.col.f32.f16.f16.f32 "
      "{%0,%1,%2,%3}, {%4,%5,%6,%7}, {%8,%9}, {%0,%1,%2,%3};\n"
      : "+f"(c[0]), "+f"(c[1]), "+f"(c[2]), "+f"(c[3])
      : "r"(a[0]), "r"(a[1]), "r"(a[2]), "r"(a[3]), "r"(b[0]), "r"(b[1]));
}
__device__ __forceinline__ void ldsm_x4(uint32_t& r0, uint32_t& r1, uint32_t& r2, uint32_t& r3,
                                        uint32_t addr){
    asm volatile("ldmatrix.sync.aligned.m8n8.x4.shared.b16 {%0,%1,%2,%3}, [%4];"
                 : "=r"(r0), "=r"(r1), "=r"(r2), "=r"(r3) : "r"(addr));
}
__device__ __forceinline__ void ldsm_x4_t(uint32_t& r0, uint32_t& r1, uint32_t& r2, uint32_t& r3,
                                          uint32_t addr){
    asm volatile("ldmatrix.sync.aligned.m8n8.x4.trans.shared.b16 {%0,%1,%2,%3}, [%4];"
                 : "=r"(r0), "=r"(r1), "=r"(r2), "=r"(r3) : "r"(addr));
}
__device__ __forceinline__ void cpa16h(__half* smem, const __half* gmem, bool pred){
    uint32_t s = (uint32_t)__cvta_generic_to_shared(smem);
    int sz = pred ? 16 : 0;
    asm volatile("cp.async.cg.shared.global [%0], [%1], 16, %2;\n"
                 :: "r"(s), "l"(gmem), "r"(sz));
}
#define CP_COMMIT() asm volatile("cp.async.commit_group;\n")
template<int N> __device__ __forceinline__ void cp_wait(){
    asm volatile("cp.async.wait_group %0;\n" :: "n"(N));
}

__device__ __forceinline__ float block_sum_256(float v){
    __shared__ float red[8];
    __shared__ float total;
    #pragma unroll
    for (int o = 16; o; o >>= 1) v += __shfl_xor_sync(0xffffffffu, v, o);
    if ((threadIdx.x & 31) == 0) red[threadIdx.x >> 5] = v;
    __syncthreads();
    if (threadIdx.x == 0){
        float s = 0.f;
        #pragma unroll
        for (int i = 0; i < 8; i++) s += red[i];
        total = s;
    }
    __syncthreads();
    float r = total;
    __syncthreads();
    return r;
}

// ---------------- streaming fp32 -> fp16 convert ----------------
__global__ __launch_bounds__(256)
void cvt16(const float4* __restrict__ src, uint4* __restrict__ dst, long long n8){
    for (long long i = blockIdx.x*256LL + threadIdx.x; i < n8; i += gridDim.x*256LL){
        float4 v0 = src[2*i], v1 = src[2*i+1];
        __half2 a = __floats2half2_rn(v0.x, v0.y);
        __half2 b = __floats2half2_rn(v0.z, v0.w);
        __half2 c = __floats2half2_rn(v1.x, v1.y);
        __half2 d = __floats2half2_rn(v1.z, v1.w);
        uint4 o;
        o.x = *(uint32_t*)&a; o.y = *(uint32_t*)&b;
        o.z = *(uint32_t*)&c; o.w = *(uint32_t*)&d;
        dst[i] = o;
    }
}

__global__ void concat_bias(const float* bq, const float* bk, const float* bv, float* dst){
    int i = blockIdx.x*256 + threadIdx.x;
    if (i < NHEAD*HEADD) dst[i] = bq[i];
    else if (i < NHEAD*HEADD + NKVH*HEADD) dst[i] = bk[i - NHEAD*HEADD];
    else if (i < QKVN) dst[i] = bv[i - NHEAD*HEADD - NKVH*HEADD];
}

// ---------------- LayerNorm ----------------
__global__ __launch_bounds__(256)
void ln_kernel(const float* __restrict__ x, const float* __restrict__ w,
               const float* __restrict__ b,
               float* __restrict__ yraw, __half* __restrict__ yh){
    long long row = blockIdx.x;
    const float* xr = x + row * HDIM;
    float v[8]; float s = 0.f;
    #pragma unroll
    for (int i = 0; i < 8; i++){ v[i] = xr[threadIdx.x + 256*i]; s += v[i]; }
    float mean = block_sum_256(s) * (1.f/HDIM);
    float ss = 0.f;
    #pragma unroll
    for (int i = 0; i < 8; i++){ float d = v[i]-mean; ss += d*d; }
    float var = block_sum_256(ss) * (1.f/HDIM);
    float rstd = rsqrtf(var + LNEPS);
    #pragma unroll
    for (int i = 0; i < 8; i++){
        int c = threadIdx.x + 256*i;
        float o = (v[i]-mean)*rstd*w[c] + b[c];
        if (yraw) yraw[row*HDIM + c] = o;
        yh[row*HDIM + c] = __float2half(o);
    }
}

// ---------------- fp16 GEMM: ldmatrix A + ldmatrix.trans B ----------------
struct GemmSegs {
    int end[3];
    const __half* B[3];
    int ldb[3];
};

#define GA_STG (128*40)
#define GB_STG (32*264)
#define GB_BASE (3*GA_STG)
#define GEMM_SMEM_BYTES ((GB_BASE + 3*GB_STG)*2)

__global__ __launch_bounds__(256)
void gemm_f16(const __half* __restrict__ A, int lda,
              GemmSegs segs, long long bStride,
              float* __restrict__ Cf, __half* __restrict__ Ch, int ldc,
              const float* __restrict__ bias, const float* __restrict__ resid,
              int M, int K,
              const int* __restrict__ rowidx,
              const int* __restrict__ counts,
              const int* __restrict__ offsets)
{
    extern __shared__ __half hsm[];
#define ASH(st, r, c) hsm[(st)*GA_STG + (r)*40 + (c)]
#define BSH(st, k, c) hsm[GB_BASE + (st)*GB_STG + (k)*264 + (c)]

    int e = blockIdx.z;
    int rowStart = 0, Mm = M;
    if (counts){ Mm = counts[e]; rowStart = offsets[e]; }
    int mbase = blockIdx.y * 128;
    if (mbase >= Mm) return;
    int nbase = blockIdx.x * 256;

    int s = 0;
    if (nbase >= segs.end[0]) s = 1;
    if (nbase >= segs.end[1]) s = 2;
    int segStart = (s == 0) ? 0 : segs.end[s-1];
    int ln = nbase - segStart;
    const __half* Bp = segs.B[s] + (long long)e * bStride + ln;
    int ldb = segs.ldb[s];

    int tid  = threadIdx.x;
    int lane = tid & 31, wid = tid >> 5;
    int warpM = wid >> 2, warpN = wid & 3;
    int g = lane >> 2, t4 = lane & 3;

    int ar = tid >> 1, hsel = tid & 1;
    bool aval = (mbase + ar < Mm);
    int arow = 0;
    if (aval) arow = rowidx ? rowidx[rowStart + mbase + ar] : (rowStart + mbase + ar);
    const __half* aptr = A + (long long)arow * lda + hsel*16;
    int brow = tid >> 3, bch = tid & 7;

    uint32_t smbase = (uint32_t)__cvta_generic_to_shared(hsm);
    int a_m = (lane & 7) + 8*((lane >> 3) & 1);
    int a_k = 8*((lane >> 4) & 1);
    uint32_t asm0 = smbase + (uint32_t)((warpM*64 + a_m)*40 + a_k)*2;
    int k_off = (lane & 7) + 8*((lane >> 3) & 1);
    int c_off = warpN*64 + 8*((lane >> 4) & 1);
    uint32_t bsm0 = smbase + GB_BASE*2 + (uint32_t)(k_off*264 + c_off)*2;

    float acc[32][4];
    #pragma unroll
    for (int i = 0; i < 32; i++)
        #pragma unroll
        for (int j = 0; j < 4; j++) acc[i][j] = 0.f;

    int nk = K >> 5;

#define GEMM_ISSUE(KT, ST) do {                                               \
        cpa16h(&ASH(ST, ar, hsel*16),     aptr + (KT)*32,     aval);          \
        cpa16h(&ASH(ST, ar, hsel*16 + 8), aptr + (KT)*32 + 8, aval);          \
        _Pragma("unroll")                                                     \
        for (int i = 0; i < 4; i++){                                          \
            int c8 = (bch + 8*i)*8;                                           \
            cpa16h(&BSH(ST, brow, c8),                                        \
                   Bp + (long long)((KT)*32 + brow)*ldb + c8, true);          \
        }                                                                     \
    } while(0)

    GEMM_ISSUE(0, 0); CP_COMMIT();
    GEMM_ISSUE(1, 1); CP_COMMIT();

    int cur = 0;
    for (int kt = 0; kt < nk; ++kt){
        if (kt + 1 < nk) cp_wait<1>(); else cp_wait<0>();
        __syncthreads();
        if (kt + 2 < nk){
            int nxt = cur + 2; if (nxt >= 3) nxt -= 3;
            GEMM_ISSUE(kt+2, nxt); CP_COMMIT();
        }

        #pragma unroll
        for (int ks = 0; ks < 2; ++ks){
            uint32_t af[4][4], bf[8][2];
            uint32_t aadr = asm0 + (uint32_t)cur*(GA_STG*2) + (uint32_t)(ks*16*2);
            #pragma unroll
            for (int ma = 0; ma < 4; ma++){
                ldsm_x4(af[ma][0], af[ma][1], af[ma][2], af[ma][3],
                        aadr + (uint32_t)(ma*16*40*2));
            }
            uint32_t badr = bsm0 + (uint32_t)cur*(GB_STG*2) + (uint32_t)(ks*16*264*2);
            #pragma unroll
            for (int p = 0; p < 4; p++){
                ldsm_x4_t(bf[2*p][0], bf[2*p][1], bf[2*p+1][0], bf[2*p+1][1],
                          badr + (uint32_t)(p*16*2));
            }
            #pragma unroll
            for (int ma = 0; ma < 4; ma++)
                #pragma unroll
                for (int na = 0; na < 8; na++)
                    mma_f16(acc[ma*8+na], af[ma], bf[na]);
        }
        cur = cur + 1; if (cur >= 3) cur -= 3;
    }

    #pragma unroll
    for (int ma = 0; ma < 4; ma++){
        #pragma unroll
        for (int na = 0; na < 8; na++){
            float* a4 = acc[ma*8+na];
            #pragma unroll
            for (int half_ = 0; half_ < 2; half_++){
                int lrow = warpM*64 + ma*16 + g + (half_ ? 8 : 0);
                int gcol = nbase + warpN*64 + na*8 + 2*t4;
                int gr = mbase + lrow;
                if (gr < Mm){
                    long long orow = rowStart + gr;
                    float v0 = a4[half_*2+0];
                    float v1 = a4[half_*2+1];
                    if (bias){ v0 += bias[gcol]; v1 += bias[gcol+1]; }
                    if (resid){
                        const float* rp = &resid[orow*(long long)ldc + gcol];
                        v0 += rp[0]; v1 += rp[1];
                    }
                    if (Cf){
                        *(float2*)&Cf[orow*(long long)ldc + gcol] = make_float2(v0, v1);
                    } else {
                        *(__half2*)&Ch[orow*(long long)ldc + gcol] = __floats2half2_rn(v0, v1);
                    }
                }
            }
        }
    }
#undef ASH
#undef BSH
#undef GEMM_ISSUE
}

// ---------------- RoPE ----------------
__global__ __launch_bounds__(256)
void rope_kernel(__half* __restrict__ qkv, const int* __restrict__ pos_ids){
    int idx = blockIdx.x*256 + threadIdx.x;
    const int total = NTOK*(NHEAD+NKVH)*64;
    if (idx >= total) return;
    int j    = idx & 63;
    int rest = idx >> 6;
    int head = rest % (NHEAD+NKVH);
    int t    = rest / (NHEAD+NKVH);
    __half* p;
    if (head < NHEAD) p = qkv + (long long)t*QKVN + head*HEADD;
    else              p = qkv + (long long)t*QKVN + NHEAD*HEADD + (head-NHEAD)*HEADD;
    double inv = exp((double)j * -0.21586735246819178);
    float th = (float)pos_ids[t] * (float)inv;
    float sn, cs; sincosf(th, &sn, &cs);
    float x0 = __half2float(p[j]), x1 = __half2float(p[j+64]);
    p[j]    = __float2half(x0*cs - x1*sn);
    p[j+64] = __float2half(x1*cs + x0*sn);
}

// ---------------- fp16 tensor-core flash attention ----------------
#define FKT 32
#define FL_PS_F   (64*36)
#define FL_FLOATS (FL_PS_F + 64*3 + 32)
#define FL_QS_H   0
#define FL_KS_H   (FL_QS_H + 64*136)
#define FL_VS_H   (FL_KS_H + FKT*136)
#define FL_PH_H   (FL_VS_H + FKT*136)
#define FL_HALVES (FL_PH_H + 64*40)
#define FL_SMEM_BYTES (FL_FLOATS*4 + FL_HALVES*2)

__global__ __launch_bounds__(256, 2)
void flash_kernel(const __half* __restrict__ qkv, const int* __restrict__ amask,
                  __half* __restrict__ O)
{
    extern __shared__ float sm[];
    float* Ps   = sm;
    float* mrow = sm + FL_PS_F;
    float* lrow = mrow + 64;
    float* srow = lrow + 64;
    int*   mk   = (int*)(srow + 64);
    __half* hb  = (__half*)(sm + FL_FLOATS);
    __half* Qs = hb + FL_QS_H;
    __half* Ks = hb + FL_KS_H;
    __half* Vs = hb + FL_VS_H;
    __half* Ph = hb + FL_PH_H;

    int qt = blockIdx.x;
    int bh = blockIdx.y;
    int b  = bh >> 4, h = bh & 15;
    int kvh = h >> 2;
    int tid = threadIdx.x;
    int lane = tid & 31, wid = tid >> 5;
    int g = lane >> 2, t4 = lane & 3;
    int mS = wid & 3;
    int nH = wid >> 2;

    int vk = (lane & 7) + 8*((lane >> 3) & 1);
    int vc = 8*((lane >> 4) & 1);
    uint32_t vbase = (uint32_t)__cvta_generic_to_shared(Vs) + (uint32_t)(vk*136 + 64*nH + vc)*2;

    for (int e2 = tid; e2 < 64*64; e2 += 256){
        int row = e2 >> 6; int d2 = (e2 & 63)*2;
        *(uint32_t*)&Qs[row*136 + d2] =
            *(const uint32_t*)&qkv[(long long)(b*SEQ + qt*64 + row)*QKVN + h*HEADD + d2];
    }
    if (tid < 64){ mrow[tid] = -1e30f; lrow[tid] = 0.f; }

    float oacc[8][4];
    #pragma unroll
    for (int i = 0; i < 8; i++)
        #pragma unroll
        for (int j = 0; j < 4; j++) oacc[i][j] = 0.f;

    const float iscale = 0.08838834764831843f;

    int nkt = 2*qt + 2;
    for (int kt = 0; kt < nkt; ++kt){
        __syncthreads();
        for (int e2 = tid; e2 < FKT*64; e2 += 256){
            int kk = e2 >> 6; int d2 = (e2 & 63)*2;
            long long base = (long long)(b*SEQ + kt*FKT + kk)*QKVN + NHEAD*HEADD + kvh*HEADD;
            *(uint32_t*)&Ks[kk*136 + d2] = *(const uint32_t*)&qkv[base + d2];
            *(uint32_t*)&Vs[kk*136 + d2] = *(const uint32_t*)&qkv[base + NKVH*HEADD + d2];
        }
        if (tid < FKT) mk[tid] = amask[b*SEQ + kt*FKT + tid];
        __syncthreads();

        float sacc[2][4];
        #pragma unroll
        for (int i = 0; i < 2; i++)
            #pragma unroll
            for (int j = 0; j < 4; j++) sacc[i][j] = 0.f;
        #pragma unroll
        for (int ks = 0; ks < 8; ++ks){
            int k0 = ks*16;
            uint32_t a[4];
            int r = 16*mS;
            a[0] = *(const uint32_t*)&Qs[(r+g  )*136 + k0 + 2*t4    ];
            a[1] = *(const uint32_t*)&Qs[(r+g+8)*136 + k0 + 2*t4    ];
            a[2] = *(const uint32_t*)&Qs[(r+g  )*136 + k0 + 2*t4 + 8];
            a[3] = *(const uint32_t*)&Qs[(r+g+8)*136 + k0 + 2*t4 + 8];
            #pragma unroll
            for (int j = 0; j < 2; j++){
                int c = 16*nH + 8*j + g;
                uint32_t bfr[2];
                bfr[0] = *(const uint32_t*)&Ks[c*136 + k0 + 2*t4    ];
                bfr[1] = *(const uint32_t*)&Ks[c*136 + k0 + 2*t4 + 8];
                mma_f16(sacc[j], a, bfr);
            }
        }
        #pragma unroll
        for (int j = 0; j < 2; j++){
            #pragma unroll
            for (int cr = 0; cr < 4; cr++){
                int row = 16*mS + g + ((cr >= 2) ? 8 : 0);
                int col = 16*nH + 8*j + 2*t4 + (cr & 1);
                int sq = qt*64 + row, sk = kt*FKT + col;
                float vv = sacc[j][cr]*iscale;
                if (sk > sq || mk[col] == 0) vv = -1e30f;
                Ps[row*36 + col] = vv;
            }
        }
        __syncthreads();

        if (tid < 64){
            int r = tid;
            float mo = mrow[r], mx = mo;
            #pragma unroll 8
            for (int kk = 0; kk < FKT; kk++) mx = fmaxf(mx, Ps[r*36+kk]);
            float sc = __expf(mo - mx);
            float ssum = 0.f;
            #pragma unroll 8
            for (int kk = 0; kk < FKT; kk++){
                float p = __expf(Ps[r*36+kk] - mx);
                ssum += p;
                Ph[r*40+kk] = __float2half(p);
            }
            lrow[r] = lrow[r]*sc + ssum;
            mrow[r] = mx;
            srow[r] = sc;
        }
        __syncthreads();

        {
            float sc0 = srow[16*mS + g];
            float sc1 = srow[16*mS + g + 8];
            #pragma unroll
            for (int j = 0; j < 8; j++){
                oacc[j][0] *= sc0; oacc[j][1] *= sc0;
                oacc[j][2] *= sc1; oacc[j][3] *= sc1;
            }
        }
        #pragma unroll
        for (int ks = 0; ks < 2; ++ks){
            int k0 = ks*16 + 2*t4;
            uint32_t a[4];
            int r = 16*mS;
            a[0] = *(const uint32_t*)&Ph[(r+g  )*40 + k0    ];
            a[1] = *(const uint32_t*)&Ph[(r+g+8)*40 + k0    ];
            a[2] = *(const uint32_t*)&Ph[(r+g  )*40 + k0 + 8];
            a[3] = *(const uint32_t*)&Ph[(r+g+8)*40 + k0 + 8];
            uint32_t badr = vbase + (uint32_t)(ks*16*136*2);
            uint32_t bf[8][2];
            #pragma unroll
            for (int p = 0; p < 4; p++){
                ldsm_x4_t(bf[2*p][0], bf[2*p][1], bf[2*p+1][0], bf[2*p+1][1],
                          badr + (uint32_t)(p*16*2));
            }
            #pragma unroll
            for (int j = 0; j < 8; j++)
                mma_f16(oacc[j], a, bf[j]);
        }
    }

    #pragma unroll
    for (int j = 0; j < 8; j++){
        #pragma unroll
        for (int half_ = 0; half_ < 2; half_++){
            int row = 16*mS + g + (half_ ? 8 : 0);
            int col = 64*nH + 8*j + 2*t4;
            int sq = qt*64 + row;
            float inv = 1.f / lrow[row];
            __half2 o2 = __floats2half2_rn(oacc[j][half_*2+0]*inv, oacc[j][half_*2+1]*inv);
            *(__half2*)&O[(((long long)(b*SEQ + sq))*NHEAD + h)*HEADD + col] = o2;
        }
    }
}

// ---------------- gate + top2 (raw fp32) ----------------
__global__ __launch_bounds__(256)
void gate_kernel(const float* __restrict__ x2, const float* __restrict__ gw,
                 int* __restrict__ e01, float* __restrict__ w01){
    long long t = blockIdx.x;
    const float* xr = x2 + t*HDIM;
    float part[NEXP];
    #pragma unroll
    for (int e = 0; e < NEXP; e++) part[e] = 0.f;
    for (int hh = threadIdx.x; hh < HDIM; hh += 256){
        float xv = xr[hh];
        const float* gp = gw + (long long)hh*NEXP;
        #pragma unroll
        for (int e = 0; e < NEXP; e++) part[e] += xv*gp[e];
    }
    __shared__ float red[8][NEXP];
    #pragma unroll
    for (int e = 0; e < NEXP; e++){
        float v = part[e];
        #pragma unroll
        for (int o = 16; o; o >>= 1) v += __shfl_xor_sync(0xffffffffu, v, o);
        if ((threadIdx.x & 31) == 0) red[threadIdx.x >> 5][e] = v;
    }
    __syncthreads();
    if (threadIdx.x == 0){
        float lg[NEXP];
        #pragma unroll
        for (int e = 0; e < NEXP; e++){
            float s = 0.f;
            #pragma unroll
            for (int w8 = 0; w8 < 8; w8++) s += red[w8][e];
            lg[e] = s;
        }
        int b0 = 0;
        #pragma unroll
        for (int e = 1; e < NEXP; e++) if (lg[e] > lg[b0]) b0 = e;
        int b1 = -1;
        #pragma unroll
        for (int e = 0; e < NEXP; e++)
            if (e != b0 && (b1 < 0 || lg[e] > lg[b1])) b1 = e;
        float t0 = 1.f / (1.f + expf(lg[b1] - lg[b0]));
        e01[2*t] = b0; e01[2*t+1] = b1;
        w01[2*t] = t0; w01[2*t+1] = 1.f - t0;
    }
}

// ---------------- routing ----------------
__global__ void route_count_kernel(const int* __restrict__ e01,
                                   int* __restrict__ counts, int* __restrict__ pos01){
    int t = blockIdx.x*blockDim.x + threadIdx.x;
    if (t < NTOK){
        pos01[2*t]   = atomicAdd(&counts[e01[2*t]],   1);
        pos01[2*t+1] = atomicAdd(&counts[e01[2*t+1]], 1);
    }
}
__global__ void route_offset_kernel(const int* __restrict__ counts, int* __restrict__ offsets){
    if (threadIdx.x == 0 && blockIdx.x == 0){
        int s = 0;
        for (int e = 0; e < NEXP; e++){ offsets[e] = s; s += counts[e]; }
    }
}
__global__ void route_scatter_kernel(const int* __restrict__ e01, const int* __restrict__ pos01,
                                     const int* __restrict__ offsets,
                                     int* __restrict__ toklist, int* __restrict__ slot01){
    int t = blockIdx.x*blockDim.x + threadIdx.x;
    if (t < NTOK){
        #pragma unroll
        for (int j = 0; j < 2; j++){
            int sl = offsets[e01[2*t+j]] + pos01[2*t+j];
            toklist[sl] = t;
            slot01[2*t+j] = sl;
        }
    }
}

// ---------------- act = silu(h1)*h3 ----------------
__global__ __launch_bounds__(256)
void silu_mul_kernel(const __half* __restrict__ h13, __half* __restrict__ act){
    long long n2 = (long long)NSLOT*FFN/2;
    for (long long i = blockIdx.x*256LL + threadIdx.x; i < n2; i += gridDim.x*256LL){
        long long slot = i >> 11;
        int f2 = (int)(i & (FFN/2 - 1));
        __half2 a = *(const __half2*)&h13[slot*(2*FFN) + f2*2];
        __half2 c = *(const __half2*)&h13[slot*(2*FFN) + FFN + f2*2];
        float v0 = __half2float(a.x), v1 = __half2float(a.y);
        float u0 = __half2float(c.x), u1 = __half2float(c.y);
        float r0 = v0 / (1.f + expf(-v0)) * u0;
        float r1 = v1 / (1.f + expf(-v1)) * u1;
        *(__half2*)&act[i*2] = __floats2half2_rn(r0, r1);
    }
}

// ---------------- final combine ----------------
__global__ __launch_bounds__(256)
void combine_kernel(const float* __restrict__ h, const float* __restrict__ eo,
                    const int* __restrict__ slot01, const float* __restrict__ w01,
                    float* __restrict__ out){
    long long idx = blockIdx.x*256LL + threadIdx.x;
    if (idx >= (long long)NTOK*HDIM) return;
    int t = (int)(idx >> 11);
    int c = (int)(idx & 2047);
    float v = h[idx];
    v += w01[2*t]   * eo[(long long)slot01[2*t]  *HDIM + c];
    v += w01[2*t+1] * eo[(long long)slot01[2*t+1]*HDIM + c];
    out[idx] = v;
}

// ---------------- launch ----------------
extern "C" void kernel_launch(void* const* d_in, const int* in_sizes, int n_in,
                              void* d_out, int out_size){
    const float* hidden = (const float*)d_in[0];
    const int*   amask  = (const int*)  d_in[1];
    const int*   posids = (const int*)  d_in[2];
    const float* ln1w = (const float*)d_in[3];
    const float* ln1b = (const float*)d_in[4];
    const float* ln2w = (const float*)d_in[5];
    const float* ln2b = (const float*)d_in[6];
    const float* wq = (const float*)d_in[7];
    const float* bq = (const float*)d_in[8];
    const float* wk = (const float*)d_in[9];
    const float* bk = (const float*)d_in[10];
    const float* wv = (const float*)d_in[11];
    const float* bv = (const float*)d_in[12];
    const float* wo = (const float*)d_in[13];
    const float* bo = (const float*)d_in[14];
    const float* gatew = (const float*)d_in[15];
    const float* w1 = (const float*)d_in[16];
    const float* w2 = (const float*)d_in[17];
    const float* w3 = (const float*)d_in[18];
    float* out = (float*)d_out;

    __half *xln1h, *qkvh, *attnh, *xln2h, *h13h, *acth;
    __half *wqh, *wkh, *wvh, *woh, *w1h, *w3h, *w2h;
    float *hbuf, *xln2, *eo, *w01, *bqkv;
    int *e01, *pos01, *counts, *offsets, *toklist, *slot01;
    cudaGetSymbolAddress((void**)&xln1h, g_xln1h);
    cudaGetSymbolAddress((void**)&qkvh, g_qkvh);
    cudaGetSymbolAddress((void**)&attnh, g_attnh);
    cudaGetSymbolAddress((void**)&hbuf, g_h);
    cudaGetSymbolAddress((void**)&xln2, g_xln2);
    cudaGetSymbolAddress((void**)&xln2h, g_xln2h);
    cudaGetSymbolAddress((void**)&h13h, g_h13h);
    cudaGetSymbolAddress((void**)&acth, g_acth);
    cudaGetSymbolAddress((void**)&eo, g_eo);
    cudaGetSymbolAddress((void**)&wqh, g_wqh);
    cudaGetSymbolAddress((void**)&wkh, g_wkh);
    cudaGetSymbolAddress((void**)&wvh, g_wvh);
    cudaGetSymbolAddress((void**)&woh, g_woh);
    cudaGetSymbolAddress((void**)&w1h, g_w1h);
    cudaGetSymbolAddress((void**)&w3h, g_w3h);
    cudaGetSymbolAddress((void**)&w2h, g_w2h);
    cudaGetSymbolAddress((void**)&bqkv, g_bqkv);
    cudaGetSymbolAddress((void**)&e01, g_e01);
    cudaGetSymbolAddress((void**)&w01, g_w01);
    cudaGetSymbolAddress((void**)&pos01, g_pos01);
    cudaGetSymbolAddress((void**)&counts, g_counts);
    cudaGetSymbolAddress((void**)&offsets, g_offsets);
    cudaGetSymbolAddress((void**)&toklist, g_toklist);
    cudaGetSymbolAddress((void**)&slot01, g_slot01);

    cudaFuncSetAttribute(flash_kernel, cudaFuncAttributeMaxDynamicSharedMemorySize, FL_SMEM_BYTES);
    cudaFuncSetAttribute(gemm_f16,    cudaFuncAttributeMaxDynamicSharedMemorySize, GEMM_SMEM_BYTES);

    static cudaStream_t s2 = nullptr;
    static cudaEvent_t evFork = nullptr, evJoin1 = nullptr, evJoin2 = nullptr;
    if (!s2){
        cudaStreamCreateWithFlags(&s2, cudaStreamNonBlocking);
        cudaEventCreateWithFlags(&evFork, cudaEventDisableTiming);
        cudaEventCreateWithFlags(&evJoin1, cudaEventDisableTiming);
        cudaEventCreateWithFlags(&evJoin2, cudaEventDisableTiming);
    }

    auto cvt = [&](cudaStream_t st, const float* s, __half* d, long long n){
        long long n8 = n >> 3;
        int nb = (int)((n8 + 255) / 256);
        if (nb > 32768) nb = 32768;
        cvt16<<<nb, 256, 0, st>>>((const float4*)s, (uint4*)d, n8);
    };

    // 0a) attention weights on main stream
    cvt(0, wq, wqh, (long long)HDIM*NHEAD*HEADD);
    cvt(0, wk, wkh, (long long)HDIM*NKVH*HEADD);
    cvt(0, wv, wvh, (long long)HDIM*NKVH*HEADD);
    cvt(0, wo, woh, (long long)HDIM*HDIM);
    concat_bias<<<(QKVN+255)/256, 256>>>(bq, bk, bv, bqkv);

    // 0b) fork: MoE conversion on side stream; split joins (w1/w3 before up-proj,
    //     w2 only before down-proj so its conversion overlaps the up-proj GEMM)
    cudaEventRecord(evFork, 0);
    cudaStreamWaitEvent(s2, evFork, 0);
    cvt(s2, w1, w1h, (long long)NEXP*HDIM*FFN);
    cvt(s2, w3, w3h, (long long)NEXP*HDIM*FFN);
    cudaEventRecord(evJoin1, s2);
    cvt(s2, w2, w2h, (long long)NEXP*FFN*HDIM);
    cudaEventRecord(evJoin2, s2);

    // 1) LN1
    ln_kernel<<<NTOK, 256>>>(hidden, ln1w, ln1b, nullptr, xln1h);

    // 2) fused QKV projection
    {
        GemmSegs sg;
        sg.end[0] = NHEAD*HEADD; sg.end[1] = NHEAD*HEADD + NKVH*HEADD; sg.end[2] = QKVN;
        sg.B[0] = wqh; sg.B[1] = wkh; sg.B[2] = wvh;
        sg.ldb[0] = NHEAD*HEADD; sg.ldb[1] = NKVH*HEADD; sg.ldb[2] = NKVH*HEADD;
        gemm_f16<<<dim3(QKVN/256, NTOK/128, 1), 256, GEMM_SMEM_BYTES>>>(
            xln1h, HDIM, sg, 0, nullptr, qkvh, QKVN, bqkv, nullptr,
            NTOK, HDIM, nullptr, nullptr, nullptr);
    }

    // 3) RoPE
    {
        int total = NTOK*(NHEAD+NKVH)*64;
        rope_kernel<<<(total+255)/256, 256>>>(qkvh, posids);
    }

    // 4) flash attention
    flash_kernel<<<dim3(SEQ/64, BATCH*NHEAD), 256, FL_SMEM_BYTES>>>(qkvh, amask, attnh);

    // 5) O projection + residual
    {
        GemmSegs sg;
        sg.end[0] = HDIM; sg.end[1] = HDIM; sg.end[2] = HDIM;
        sg.B[0] = woh; sg.B[1] = woh; sg.B[2] = woh;
        sg.ldb[0] = HDIM; sg.ldb[1] = HDIM; sg.ldb[2] = HDIM;
        gemm_f16<<<dim3(HDIM/256, NTOK/128, 1), 256, GEMM_SMEM_BYTES>>>(
            attnh, NHEAD*HEADD, sg, 0, hbuf, nullptr, HDIM, bo, hidden,
            NTOK, NHEAD*HEADD, nullptr, nullptr, nullptr);
    }

    // 6) LN2
    ln_kernel<<<NTOK, 256>>>(hbuf, ln2w, ln2b, xln2, xln2h);
    // 7) gate + top2
    gate_kernel<<<NTOK, 256>>>(xln2, gatew, e01, w01);
    // 8) routing
    cudaMemsetAsync(counts, 0, NEXP*sizeof(int));
    route_count_kernel<<<(NTOK+255)/256, 256>>>(e01, counts, pos01);
    route_offset_kernel<<<1, 32>>>(counts, offsets);
    route_scatter_kernel<<<(NTOK+255)/256, 256>>>(e01, pos01, offsets, toklist, slot01);

    // join 1: w1/w3 fp16 weights ready
    cudaStreamWaitEvent(0, evJoin1, 0);

    // 9) expert up-projections -> fp16 h13
    {
        GemmSegs sg;
        sg.end[0] = FFN; sg.end[1] = 2*FFN; sg.end[2] = 2*FFN;
        sg.B[0] = w1h; sg.B[1] = w3h; sg.B[2] = w3h;
        sg.ldb[0] = FFN; sg.ldb[1] = FFN; sg.ldb[2] = FFN;
        gemm_f16<<<dim3(2*FFN/256, NTOK/128, NEXP), 256, GEMM_SMEM_BYTES>>>(
            xln2h, HDIM, sg, (long long)HDIM*FFN, nullptr, h13h, 2*FFN, nullptr, nullptr,
            NTOK, HDIM, toklist, counts, offsets);
    }

    // 10) act = silu(h1)*h3
    silu_mul_kernel<<<8192, 256>>>(h13h, acth);

    // join 2: w2 fp16 weights ready (converted during up-proj)
    cudaStreamWaitEvent(0, evJoin2, 0);

    // 11) eo = act @ w2(e)
    {
        GemmSegs sg;
        sg.end[0] = HDIM; sg.end[1] = HDIM; sg.end[2] = HDIM;
        sg.B[0] = w2h; sg.B[1] = w2h; sg.B[2] = w2h;
        sg.ldb[0] = HDIM; sg.ldb[1] = HDIM; sg.ldb[2] = HDIM;
        gemm_f16<<<dim3(HDIM/256, NTOK/128, NEXP), 256, GEMM_SMEM_BYTES>>>(
            acth, FFN, sg, (long long)FFN*HDIM, eo, nullptr, HDIM, nullptr, nullptr,
            NTOK, FFN, nullptr, counts, offsets);
    }

    // 12) combine
    combine_kernel<<<(int)(((long long)NTOK*HDIM + 255)/256), 256>>>(hbuf, eo, slot01, w01, out);
}

// round 15
// speedup vs baseline: 1.0241x; 1.0016x over previous
#include <cuda_runtime.h>
#include <cuda_fp16.h>
#include <math.h>
#include <stdint.h>

// ---------------- problem constants ----------------
#define BATCH 2
#define SEQ   1024
#define HDIM  2048
#define NHEAD 16
#define NKVH  4
#define HEADD 128
#define FFN   4096
#define NEXP  8
#define NTOK  (BATCH*SEQ)
#define QKVN  (NHEAD*HEADD + 2*NKVH*HEADD)   // 3072
#define NSLOT (2*NTOK)
#define LNEPS 1e-5f

// ---------------- device scratch ----------------
__device__ __half g_xln1h[NTOK*HDIM];
__device__ __half g_qkvh [NTOK*QKVN];
__device__ __half g_attnh[NTOK*NHEAD*HEADD];
__device__ float  g_h    [NTOK*HDIM];
__device__ __half g_xln2h[NTOK*HDIM];
__device__ __half g_h13h [NSLOT*2*FFN];
__device__ __half g_acth [NSLOT*FFN];
__device__ float  g_eo   [NSLOT*HDIM];
// fp16 weights, ORIGINAL [K][N] layout
__device__ __half g_wqh [HDIM*NHEAD*HEADD];
__device__ __half g_wkh [HDIM*NKVH*HEADD];
__device__ __half g_wvh [HDIM*NKVH*HEADD];
__device__ __half g_woh [HDIM*HDIM];
__device__ __half g_w1h [NEXP*HDIM*FFN];
__device__ __half g_w3h [NEXP*HDIM*FFN];
__device__ __half g_w2h [NEXP*FFN*HDIM];
__device__ float  g_bqkv[QKVN];
// routing
__device__ int   g_e01 [NTOK*2];
__device__ float g_w01 [NTOK*2];
__device__ int   g_pos01[NTOK*2];
__device__ int   g_counts[NEXP];
__device__ int   g_offsets[NEXP];
__device__ int   g_toklist[NSLOT];
__device__ int   g_slot01[NTOK*2];

// ---------------- helpers ----------------
__device__ __forceinline__ void mma_f16(float* c, const uint32_t* a, const uint32_t* b){
    asm volatile(
      "mma.sync.aligned.m16n8k16.row.col.f32.f16.f16.f32 "
      "{%0,%1,%2,%3}, {%4,%5,%6,%7}, {%8,%9}, {%0,%1,%2,%3};\n"
      : "+f"(c[0]), "+f"(c[1]), "+f"(c[2]), "+f"(c[3])
      : "r"(a[0]), "r"(a[1]), "r"(a[2]), "r"(a[3]), "r"(b[0]), "r"(b[1]));
}
__device__ __forceinline__ void ldsm_x4(uint32_t& r0, uint32_t& r1, uint32_t& r2, uint32_t& r3,
                                        uint32_t addr){
    asm volatile("ldmatrix.sync.aligned.m8n8.x4.shared.b16 {%0,%1,%2,%3}, [%4];"
                 : "=r"(r0), "=r"(r1), "=r"(r2), "=r"(r3) : "r"(addr));
}
__device__ __forceinline__ void ldsm_x4_t(uint32_t& r0, uint32_t& r1, uint32_t& r2, uint32_t& r3,
                                          uint32_t addr){
    asm volatile("ldmatrix.sync.aligned.m8n8.x4.trans.shared.b16 {%0,%1,%2,%3}, [%4];"
                 : "=r"(r0), "=r"(r1), "=r"(r2), "=r"(r3) : "r"(addr));
}
__device__ __forceinline__ void cpa16h(__half* smem, const __half* gmem, bool pred){
    uint32_t s = (uint32_t)__cvta_generic_to_shared(smem);
    int sz = pred ? 16 : 0;
    asm volatile("cp.async.cg.shared.global [%0], [%1], 16, %2;\n"
                 :: "r"(s), "l"(gmem), "r"(sz));
}
#define CP_COMMIT() asm volatile("cp.async.commit_group;\n")
template<int N> __device__ __forceinline__ void cp_wait(){
    asm volatile("cp.async.wait_group %0;\n" :: "n"(N));
}

__device__ __forceinline__ float block_sum_256(float v){
    __shared__ float red[8];
    __shared__ float total;
    #pragma unroll
    for (int o = 16; o; o >>= 1) v += __shfl_xor_sync(0xffffffffu, v, o);
    if ((threadIdx.x & 31) == 0) red[threadIdx.x >> 5] = v;
    __syncthreads();
    if (threadIdx.x == 0){
        float s = 0.f;
        #pragma unroll
        for (int i = 0; i < 8; i++) s += red[i];
        total = s;
    }
    __syncthreads();
    float r = total;
    __syncthreads();
    return r;
}

// ---------------- streaming fp32 -> fp16 convert ----------------
__global__ __launch_bounds__(256)
void cvt16(const float4* __restrict__ src, uint4* __restrict__ dst, long long n8){
    for (long long i = blockIdx.x*256LL + threadIdx.x; i < n8; i += gridDim.x*256LL){
        float4 v0 = src[2*i], v1 = src[2*i+1];
        __half2 a = __floats2half2_rn(v0.x, v0.y);
        __half2 b = __floats2half2_rn(v0.z, v0.w);
        __half2 c = __floats2half2_rn(v1.x, v1.y);
        __half2 d = __floats2half2_rn(v1.z, v1.w);
        uint4 o;
        o.x = *(uint32_t*)&a; o.y = *(uint32_t*)&b;
        o.z = *(uint32_t*)&c; o.w = *(uint32_t*)&d;
        dst[i] = o;
    }
}

__global__ void concat_bias(const float* bq, const float* bk, const float* bv, float* dst){
    int i = blockIdx.x*256 + threadIdx.x;
    if (i < NHEAD*HEADD) dst[i] = bq[i];
    else if (i < NHEAD*HEADD + NKVH*HEADD) dst[i] = bk[i - NHEAD*HEADD];
    else if (i < QKVN) dst[i] = bv[i - NHEAD*HEADD - NKVH*HEADD];
}

// ---------------- LayerNorm (+ optional fused MoE gate / top-2) ----------------
__global__ __launch_bounds__(256)
void ln_kernel(const float* __restrict__ x, const float* __restrict__ w,
               const float* __restrict__ b, __half* __restrict__ yh,
               const float* __restrict__ gw,   // if non-null: fused gate
               int* __restrict__ e01, float* __restrict__ w01){
    long long row = blockIdx.x;
    const float* xr = x + row * HDIM;
    float v[8]; float s = 0.f;
    #pragma unroll
    for (int i = 0; i < 8; i++){ v[i] = xr[threadIdx.x + 256*i]; s += v[i]; }
    float mean = block_sum_256(s) * (1.f/HDIM);
    float ss = 0.f;
    #pragma unroll
    for (int i = 0; i < 8; i++){ float d = v[i]-mean; ss += d*d; }
    float var = block_sum_256(ss) * (1.f/HDIM);
    float rstd = rsqrtf(var + LNEPS);
    float ov[8];
    #pragma unroll
    for (int i = 0; i < 8; i++){
        int c = threadIdx.x + 256*i;
        ov[i] = (v[i]-mean)*rstd*w[c] + b[c];
        yh[row*HDIM + c] = __float2half(ov[i]);
    }
    if (gw){
        // gate: identical column mapping + reduction order as the old gate_kernel
        float part[NEXP];
        #pragma unroll
        for (int e = 0; e < NEXP; e++) part[e] = 0.f;
        #pragma unroll
        for (int i = 0; i < 8; i++){
            int c = threadIdx.x + 256*i;
            const float* gp = gw + (long long)c*NEXP;
            #pragma unroll
            for (int e = 0; e < NEXP; e++) part[e] += ov[i]*gp[e];
        }
        __shared__ float red[8][NEXP];
        #pragma unroll
        for (int e = 0; e < NEXP; e++){
            float vv = part[e];
            #pragma unroll
            for (int o = 16; o; o >>= 1) vv += __shfl_xor_sync(0xffffffffu, vv, o);
            if ((threadIdx.x & 31) == 0) red[threadIdx.x >> 5][e] = vv;
        }
        __syncthreads();
        if (threadIdx.x == 0){
            float lg[NEXP];
            #pragma unroll
            for (int e = 0; e < NEXP; e++){
                float ssum = 0.f;
                #pragma unroll
                for (int w8 = 0; w8 < 8; w8++) ssum += red[w8][e];
                lg[e] = ssum;
            }
            int b0 = 0;
            #pragma unroll
            for (int e = 1; e < NEXP; e++) if (lg[e] > lg[b0]) b0 = e;
            int b1 = -1;
            #pragma unroll
            for (int e = 0; e < NEXP; e++)
                if (e != b0 && (b1 < 0 || lg[e] > lg[b1])) b1 = e;
            float t0 = 1.f / (1.f + expf(lg[b1] - lg[b0]));
            e01[2*row] = b0; e01[2*row+1] = b1;
            w01[2*row] = t0; w01[2*row+1] = 1.f - t0;
        }
    }
}

// ---------------- fp16 GEMM: ldmatrix A + ldmatrix.trans B ----------------
struct GemmSegs {
    int end[3];
    const __half* B[3];
    int ldb[3];
};

#define GA_STG (128*40)
#define GB_STG (32*264)
#define GB_BASE (3*GA_STG)
#define GEMM_SMEM_BYTES ((GB_BASE + 3*GB_STG)*2)

__global__ __launch_bounds__(256)
void gemm_f16(const __half* __restrict__ A, int lda,
              GemmSegs segs, long long bStride,
              float* __restrict__ Cf, __half* __restrict__ Ch, int ldc,
              const float* __restrict__ bias, const float* __restrict__ resid,
              int M, int K,
              const int* __restrict__ rowidx,
              const int* __restrict__ counts,
              const int* __restrict__ offsets)
{
    extern __shared__ __half hsm[];
#define ASH(st, r, c) hsm[(st)*GA_STG + (r)*40 + (c)]
#define BSH(st, k, c) hsm[GB_BASE + (st)*GB_STG + (k)*264 + (c)]

    int e = blockIdx.z;
    int rowStart = 0, Mm = M;
    if (counts){ Mm = counts[e]; rowStart = offsets[e]; }
    int mbase = blockIdx.y * 128;
    if (mbase >= Mm) return;
    int nbase = blockIdx.x * 256;

    int s = 0;
    if (nbase >= segs.end[0]) s = 1;
    if (nbase >= segs.end[1]) s = 2;
    int segStart = (s == 0) ? 0 : segs.end[s-1];
    int ln = nbase - segStart;
    const __half* Bp = segs.B[s] + (long long)e * bStride + ln;
    int ldb = segs.ldb[s];

    int tid  = threadIdx.x;
    int lane = tid & 31, wid = tid >> 5;
    int warpM = wid >> 2, warpN = wid & 3;
    int g = lane >> 2, t4 = lane & 3;

    int ar = tid >> 1, hsel = tid & 1;
    bool aval = (mbase + ar < Mm);
    int arow = 0;
    if (aval) arow = rowidx ? rowidx[rowStart + mbase + ar] : (rowStart + mbase + ar);
    const __half* aptr = A + (long long)arow * lda + hsel*16;
    int brow = tid >> 3, bch = tid & 7;

    uint32_t smbase = (uint32_t)__cvta_generic_to_shared(hsm);
    int a_m = (lane & 7) + 8*((lane >> 3) & 1);
    int a_k = 8*((lane >> 4) & 1);
    uint32_t asm0 = smbase + (uint32_t)((warpM*64 + a_m)*40 + a_k)*2;
    int k_off = (lane & 7) + 8*((lane >> 3) & 1);
    int c_off = warpN*64 + 8*((lane >> 4) & 1);
    uint32_t bsm0 = smbase + GB_BASE*2 + (uint32_t)(k_off*264 + c_off)*2;

    float acc[32][4];
    #pragma unroll
    for (int i = 0; i < 32; i++)
        #pragma unroll
        for (int j = 0; j < 4; j++) acc[i][j] = 0.f;

    int nk = K >> 5;

#define GEMM_ISSUE(KT, ST) do {                                               \
        cpa16h(&ASH(ST, ar, hsel*16),     aptr + (KT)*32,     aval);          \
        cpa16h(&ASH(ST, ar, hsel*16 + 8), aptr + (KT)*32 + 8, aval);          \
        _Pragma("unroll")                                                     \
        for (int i = 0; i < 4; i++){                                          \
            int c8 = (bch + 8*i)*8;                                           \
            cpa16h(&BSH(ST, brow, c8),                                        \
                   Bp + (long long)((KT)*32 + brow)*ldb + c8, true);          \
        }                                                                     \
    } while(0)

    GEMM_ISSUE(0, 0); CP_COMMIT();
    GEMM_ISSUE(1, 1); CP_COMMIT();

    int cur = 0;
    for (int kt = 0; kt < nk; ++kt){
        if (kt + 1 < nk) cp_wait<1>(); else cp_wait<0>();
        __syncthreads();
        if (kt + 2 < nk){
            int nxt = cur + 2; if (nxt >= 3) nxt -= 3;
            GEMM_ISSUE(kt+2, nxt); CP_COMMIT();
        }

        #pragma unroll
        for (int ks = 0; ks < 2; ++ks){
            uint32_t af[4][4], bf[8][2];
            uint32_t aadr = asm0 + (uint32_t)cur*(GA_STG*2) + (uint32_t)(ks*16*2);
            #pragma unroll
            for (int ma = 0; ma < 4; ma++){
                ldsm_x4(af[ma][0], af[ma][1], af[ma][2], af[ma][3],
                        aadr + (uint32_t)(ma*16*40*2));
            }
            uint32_t badr = bsm0 + (uint32_t)cur*(GB_STG*2) + (uint32_t)(ks*16*264*2);
            #pragma unroll
            for (int p = 0; p < 4; p++){
                ldsm_x4_t(bf[2*p][0], bf[2*p][1], bf[2*p+1][0], bf[2*p+1][1],
                          badr + (uint32_t)(p*16*2));
            }
            #pragma unroll
            for (int ma = 0; ma < 4; ma++)
                #pragma unroll
                for (int na = 0; na < 8; na++)
                    mma_f16(acc[ma*8+na], af[ma], bf[na]);
        }
        cur = cur + 1; if (cur >= 3) cur -= 3;
    }

    #pragma unroll
    for (int ma = 0; ma < 4; ma++){
        #pragma unroll
        for (int na = 0; na < 8; na++){
            float* a4 = acc[ma*8+na];
            #pragma unroll
            for (int half_ = 0; half_ < 2; half_++){
                int lrow = warpM*64 + ma*16 + g + (half_ ? 8 : 0);
                int gcol = nbase + warpN*64 + na*8 + 2*t4;
                int gr = mbase + lrow;
                if (gr < Mm){
                    long long orow = rowStart + gr;
                    float v0 = a4[half_*2+0];
                    float v1 = a4[half_*2+1];
                    if (bias){ v0 += bias[gcol]; v1 += bias[gcol+1]; }
                    if (resid){
                        const float* rp = &resid[orow*(long long)ldc + gcol];
                        v0 += rp[0]; v1 += rp[1];
                    }
                    if (Cf){
                        *(float2*)&Cf[orow*(long long)ldc + gcol] = make_float2(v0, v1);
                    } else {
                        *(__half2*)&Ch[orow*(long long)ldc + gcol] = __floats2half2_rn(v0, v1);
                    }
                }
            }
        }
    }
#undef ASH
#undef BSH
#undef GEMM_ISSUE
}

// ---------------- RoPE ----------------
__global__ __launch_bounds__(256)
void rope_kernel(__half* __restrict__ qkv, const int* __restrict__ pos_ids){
    int idx = blockIdx.x*256 + threadIdx.x;
    const int total = NTOK*(NHEAD+NKVH)*64;
    if (idx >= total) return;
    int j    = idx & 63;
    int rest = idx >> 6;
    int head = rest % (NHEAD+NKVH);
    int t    = rest / (NHEAD+NKVH);
    __half* p;
    if (head < NHEAD) p = qkv + (long long)t*QKVN + head*HEADD;
    else              p = qkv + (long long)t*QKVN + NHEAD*HEADD + (head-NHEAD)*HEADD;
    double inv = exp((double)j * -0.21586735246819178);
    float th = (float)pos_ids[t] * (float)inv;
    float sn, cs; sincosf(th, &sn, &cs);
    float x0 = __half2float(p[j]), x1 = __half2float(p[j+64]);
    p[j]    = __float2half(x0*cs - x1*sn);
    p[j+64] = __float2half(x1*cs + x0*sn);
}

// ---------------- fp16 tensor-core flash attention ----------------
#define FKT 32
#define FL_PS_F   (64*36)
#define FL_FLOATS (FL_PS_F + 64*3 + 32)
#define FL_QS_H   0
#define FL_KS_H   (FL_QS_H + 64*136)
#define FL_VS_H   (FL_KS_H + FKT*136)
#define FL_PH_H   (FL_VS_H + FKT*136)
#define FL_HALVES (FL_PH_H + 64*40)
#define FL_SMEM_BYTES (FL_FLOATS*4 + FL_HALVES*2)

__global__ __launch_bounds__(256, 2)
void flash_kernel(const __half* __restrict__ qkv, const int* __restrict__ amask,
                  __half* __restrict__ O)
{
    extern __shared__ float sm[];
    float* Ps   = sm;
    float* mrow = sm + FL_PS_F;
    float* lrow = mrow + 64;
    float* srow = lrow + 64;
    int*   mk   = (int*)(srow + 64);
    __half* hb  = (__half*)(sm + FL_FLOATS);
    __half* Qs = hb + FL_QS_H;
    __half* Ks = hb + FL_KS_H;
    __half* Vs = hb + FL_VS_H;
    __half* Ph = hb + FL_PH_H;

    int qt = (gridDim.x - 1) - blockIdx.x;   // heavy causal tiles start first
    int bh = blockIdx.y;
    int b  = bh >> 4, h = bh & 15;
    int kvh = h >> 2;
    int tid = threadIdx.x;
    int lane = tid & 31, wid = tid >> 5;
    int g = lane >> 2, t4 = lane & 3;
    int mS = wid & 3;
    int nH = wid >> 2;

    int vk = (lane & 7) + 8*((lane >> 3) & 1);
    int vc = 8*((lane >> 4) & 1);
    uint32_t vbase = (uint32_t)__cvta_generic_to_shared(Vs) + (uint32_t)(vk*136 + 64*nH + vc)*2;

    for (int e2 = tid; e2 < 64*64; e2 += 256){
        int row = e2 >> 6; int d2 = (e2 & 63)*2;
        *(uint32_t*)&Qs[row*136 + d2] =
            *(const uint32_t*)&qkv[(long long)(b*SEQ + qt*64 + row)*QKVN + h*HEADD + d2];
    }
    if (tid < 64){ mrow[tid] = -1e30f; lrow[tid] = 0.f; }

    float oacc[8][4];
    #pragma unroll
    for (int i = 0; i < 8; i++)
        #pragma unroll
        for (int j = 0; j < 4; j++) oacc[i][j] = 0.f;

    const float iscale = 0.08838834764831843f;

    int nkt = 2*qt + 2;
    for (int kt = 0; kt < nkt; ++kt){
        __syncthreads();
        for (int e2 = tid; e2 < FKT*64; e2 += 256){
            int kk = e2 >> 6; int d2 = (e2 & 63)*2;
            long long base = (long long)(b*SEQ + kt*FKT + kk)*QKVN + NHEAD*HEADD + kvh*HEADD;
            *(uint32_t*)&Ks[kk*136 + d2] = *(const uint32_t*)&qkv[base + d2];
            *(uint32_t*)&Vs[kk*136 + d2] = *(const uint32_t*)&qkv[base + NKVH*HEADD + d2];
        }
        if (tid < FKT) mk[tid] = amask[b*SEQ + kt*FKT + tid];
        __syncthreads();

        float sacc[2][4];
        #pragma unroll
        for (int i = 0; i < 2; i++)
            #pragma unroll
            for (int j = 0; j < 4; j++) sacc[i][j] = 0.f;
        #pragma unroll
        for (int ks = 0; ks < 8; ++ks){
            int k0 = ks*16;
            uint32_t a[4];
            int r = 16*mS;
            a[0] = *(const uint32_t*)&Qs[(r+g  )*136 + k0 + 2*t4    ];
            a[1] = *(const uint32_t*)&Qs[(r+g+8)*136 + k0 + 2*t4    ];
            a[2] = *(const uint32_t*)&Qs[(r+g  )*136 + k0 + 2*t4 + 8];
            a[3] = *(const uint32_t*)&Qs[(r+g+8)*136 + k0 + 2*t4 + 8];
            #pragma unroll
            for (int j = 0; j < 2; j++){
                int c = 16*nH + 8*j + g;
                uint32_t bfr[2];
                bfr[0] = *(const uint32_t*)&Ks[c*136 + k0 + 2*t4    ];
                bfr[1] = *(const uint32_t*)&Ks[c*136 + k0 + 2*t4 + 8];
                mma_f16(sacc[j], a, bfr);
            }
        }
        #pragma unroll
        for (int j = 0; j < 2; j++){
            #pragma unroll
            for (int cr = 0; cr < 4; cr++){
                int row = 16*mS + g + ((cr >= 2) ? 8 : 0);
                int col = 16*nH + 8*j + 2*t4 + (cr & 1);
                int sq = qt*64 + row, sk = kt*FKT + col;
                float vv = sacc[j][cr]*iscale;
                if (sk > sq || mk[col] == 0) vv = -1e30f;
                Ps[row*36 + col] = vv;
            }
        }
        __syncthreads();

        if (tid < 64){
            int r = tid;
            float mo = mrow[r], mx = mo;
            #pragma unroll 8
            for (int kk = 0; kk < FKT; kk++) mx = fmaxf(mx, Ps[r*36+kk]);
            float sc = __expf(mo - mx);
            float ssum = 0.f;
            #pragma unroll 8
            for (int kk = 0; kk < FKT; kk++){
                float p = __expf(Ps[r*36+kk] - mx);
                ssum += p;
                Ph[r*40+kk] = __float2half(p);
            }
            lrow[r] = lrow[r]*sc + ssum;
            mrow[r] = mx;
            srow[r] = sc;
        }
        __syncthreads();

        {
            float sc0 = srow[16*mS + g];
            float sc1 = srow[16*mS + g + 8];
            #pragma unroll
            for (int j = 0; j < 8; j++){
                oacc[j][0] *= sc0; oacc[j][1] *= sc0;
                oacc[j][2] *= sc1; oacc[j][3] *= sc1;
            }
        }
        #pragma unroll
        for (int ks = 0; ks < 2; ++ks){
            int k0 = ks*16 + 2*t4;
            uint32_t a[4];
            int r = 16*mS;
            a[0] = *(const uint32_t*)&Ph[(r+g  )*40 + k0    ];
            a[1] = *(const uint32_t*)&Ph[(r+g+8)*40 + k0    ];
            a[2] = *(const uint32_t*)&Ph[(r+g  )*40 + k0 + 8];
            a[3] = *(const uint32_t*)&Ph[(r+g+8)*40 + k0 + 8];
            uint32_t badr = vbase + (uint32_t)(ks*16*136*2);
            uint32_t bf[8][2];
            #pragma unroll
            for (int p = 0; p < 4; p++){
                ldsm_x4_t(bf[2*p][0], bf[2*p][1], bf[2*p+1][0], bf[2*p+1][1],
                          badr + (uint32_t)(p*16*2));
            }
            #pragma unroll
            for (int j = 0; j < 8; j++)
                mma_f16(oacc[j], a, bf[j]);
        }
    }

    #pragma unroll
    for (int j = 0; j < 8; j++){
        #pragma unroll
        for (int half_ = 0; half_ < 2; half_++){
            int row = 16*mS + g + (half_ ? 8 : 0);
            int col = 64*nH + 8*j + 2*t4;
            int sq = qt*64 + row;
            float inv = 1.f / lrow[row];
            __half2 o2 = __floats2half2_rn(oacc[j][half_*2+0]*inv, oacc[j][half_*2+1]*inv);
            *(__half2*)&O[(((long long)(b*SEQ + sq))*NHEAD + h)*HEADD + col] = o2;
        }
    }
}

// ---------------- routing ----------------
__global__ void route_count_kernel(const int* __restrict__ e01,
                                   int* __restrict__ counts, int* __restrict__ pos01){
    int t = blockIdx.x*blockDim.x + threadIdx.x;
    if (t < NTOK){
        pos01[2*t]   = atomicAdd(&counts[e01[2*t]],   1);
        pos01[2*t+1] = atomicAdd(&counts[e01[2*t+1]], 1);
    }
}
__global__ void route_offset_kernel(const int* __restrict__ counts, int* __restrict__ offsets){
    if (threadIdx.x == 0 && blockIdx.x == 0){
        int s = 0;
        for (int e = 0; e < NEXP; e++){ offsets[e] = s; s += counts[e]; }
    }
}
__global__ void route_scatter_kernel(const int* __restrict__ e01, const int* __restrict__ pos01,
                                     const int* __restrict__ offsets,
                                     int* __restrict__ toklist, int* __restrict__ slot01){
    int t = blockIdx.x*blockDim.x + threadIdx.x;
    if (t < NTOK){
        #pragma unroll
        for (int j = 0; j < 2; j++){
            int sl = offsets[e01[2*t+j]] + pos01[2*t+j];
            toklist[sl] = t;
            slot01[2*t+j] = sl;
        }
    }
}

// ---------------- act = silu(h1)*h3 ----------------
__global__ __launch_bounds__(256)
void silu_mul_kernel(const __half* __restrict__ h13, __half* __restrict__ act){
    long long n2 = (long long)NSLOT*FFN/2;
    for (long long i = blockIdx.x*256LL + threadIdx.x; i < n2; i += gridDim.x*256LL){
        long long slot = i >> 11;
        int f2 = (int)(i & (FFN/2 - 1));
        __half2 a = *(const __half2*)&h13[slot*(2*FFN) + f2*2];
        __half2 c = *(const __half2*)&h13[slot*(2*FFN) + FFN + f2*2];
        float v0 = __half2float(a.x), v1 = __half2float(a.y);
        float u0 = __half2float(c.x), u1 = __half2float(c.y);
        float r0 = v0 / (1.f + expf(-v0)) * u0;
        float r1 = v1 / (1.f + expf(-v1)) * u1;
        *(__half2*)&act[i*2] = __floats2half2_rn(r0, r1);
    }
}

// ---------------- final combine ----------------
__global__ __launch_bounds__(256)
void combine_kernel(const float* __restrict__ h, const float* __restrict__ eo,
                    const int* __restrict__ slot01, const float* __restrict__ w01,
                    float* __restrict__ out){
    long long idx = blockIdx.x*256LL + threadIdx.x;
    if (idx >= (long long)NTOK*HDIM) return;
    int t = (int)(idx >> 11);
    int c = (int)(idx & 2047);
    float v = h[idx];
    v += w01[2*t]   * eo[(long long)slot01[2*t]  *HDIM + c];
    v += w01[2*t+1] * eo[(long long)slot01[2*t+1]*HDIM + c];
    out[idx] = v;
}

// ---------------- launch ----------------
extern "C" void kernel_launch(void* const* d_in, const int* in_sizes, int n_in,
                              void* d_out, int out_size){
    const float* hidden = (const float*)d_in[0];
    const int*   amask  = (const int*)  d_in[1];
    const int*   posids = (const int*)  d_in[2];
    const float* ln1w = (const float*)d_in[3];
    const float* ln1b = (const float*)d_in[4];
    const float* ln2w = (const float*)d_in[5];
    const float* ln2b = (const float*)d_in[6];
    const float* wq = (const float*)d_in[7];
    const float* bq = (const float*)d_in[8];
    const float* wk = (const float*)d_in[9];
    const float* bk = (const float*)d_in[10];
    const float* wv = (const float*)d_in[11];
    const float* bv = (const float*)d_in[12];
    const float* wo = (const float*)d_in[13];
    const float* bo = (const float*)d_in[14];
    const float* gatew = (const float*)d_in[15];
    const float* w1 = (const float*)d_in[16];
    const float* w2 = (const float*)d_in[17];
    const float* w3 = (const float*)d_in[18];
    float* out = (float*)d_out;

    __half *xln1h, *qkvh, *attnh, *xln2h, *h13h, *acth;
    __half *wqh, *wkh, *wvh, *woh, *w1h, *w3h, *w2h;
    float *hbuf, *eo, *w01, *bqkv;
    int *e01, *pos01, *counts, *offsets, *toklist, *slot01;
    cudaGetSymbolAddress((void**)&xln1h, g_xln1h);
    cudaGetSymbolAddress((void**)&qkvh, g_qkvh);
    cudaGetSymbolAddress((void**)&attnh, g_attnh);
    cudaGetSymbolAddress((void**)&hbuf, g_h);
    cudaGetSymbolAddress((void**)&xln2h, g_xln2h);
    cudaGetSymbolAddress((void**)&h13h, g_h13h);
    cudaGetSymbolAddress((void**)&acth, g_acth);
    cudaGetSymbolAddress((void**)&eo, g_eo);
    cudaGetSymbolAddress((void**)&wqh, g_wqh);
    cudaGetSymbolAddress((void**)&wkh, g_wkh);
    cudaGetSymbolAddress((void**)&wvh, g_wvh);
    cudaGetSymbolAddress((void**)&woh, g_woh);
    cudaGetSymbolAddress((void**)&w1h, g_w1h);
    cudaGetSymbolAddress((void**)&w3h, g_w3h);
    cudaGetSymbolAddress((void**)&w2h, g_w2h);
    cudaGetSymbolAddress((void**)&bqkv, g_bqkv);
    cudaGetSymbolAddress((void**)&e01, g_e01);
    cudaGetSymbolAddress((void**)&w01, g_w01);
    cudaGetSymbolAddress((void**)&pos01, g_pos01);
    cudaGetSymbolAddress((void**)&counts, g_counts);
    cudaGetSymbolAddress((void**)&offsets, g_offsets);
    cudaGetSymbolAddress((void**)&toklist, g_toklist);
    cudaGetSymbolAddress((void**)&slot01, g_slot01);

    cudaFuncSetAttribute(flash_kernel, cudaFuncAttributeMaxDynamicSharedMemorySize, FL_SMEM_BYTES);
    cudaFuncSetAttribute(gemm_f16,    cudaFuncAttributeMaxDynamicSharedMemorySize, GEMM_SMEM_BYTES);

    static cudaStream_t s2 = nullptr;
    static cudaEvent_t evFork = nullptr, evJoin1 = nullptr, evJoin2 = nullptr;
    if (!s2){
        cudaStreamCreateWithFlags(&s2, cudaStreamNonBlocking);
        cudaEventCreateWithFlags(&evFork, cudaEventDisableTiming);
        cudaEventCreateWithFlags(&evJoin1, cudaEventDisableTiming);
        cudaEventCreateWithFlags(&evJoin2, cudaEventDisableTiming);
    }

    auto cvt = [&](cudaStream_t st, const float* s, __half* d, long long n){
        long long n8 = n >> 3;
        int nb = (int)((n8 + 255) / 256);
        if (nb > 32768) nb = 32768;
        cvt16<<<nb, 256, 0, st>>>((const float4*)s, (uint4*)d, n8);
    };

    // 0a) attention weights on main stream
    cvt(0, wq, wqh, (long long)HDIM*NHEAD*HEADD);
    cvt(0, wk, wkh, (long long)HDIM*NKVH*HEADD);
    cvt(0, wv, wvh, (long long)HDIM*NKVH*HEADD);
    cvt(0, wo, woh, (long long)HDIM*HDIM);
    concat_bias<<<(QKVN+255)/256, 256>>>(bq, bk, bv, bqkv);

    // 0b) fork: MoE conversion on side stream; split joins
    cudaEventRecord(evFork, 0);
    cudaStreamWaitEvent(s2, evFork, 0);
    cvt(s2, w1, w1h, (long long)NEXP*HDIM*FFN);
    cvt(s2, w3, w3h, (long long)NEXP*HDIM*FFN);
    cudaEventRecord(evJoin1, s2);
    cvt(s2, w2, w2h, (long long)NEXP*FFN*HDIM);
    cudaEventRecord(evJoin2, s2);

    // 1) LN1 (no gate)
    ln_kernel<<<NTOK, 256>>>(hidden, ln1w, ln1b, xln1h, nullptr, nullptr, nullptr);

    // 2) fused QKV projection
    {
        GemmSegs sg;
        sg.end[0] = NHEAD*HEADD; sg.end[1] = NHEAD*HEADD + NKVH*HEADD; sg.end[2] = QKVN;
        sg.B[0] = wqh; sg.B[1] = wkh; sg.B[2] = wvh;
        sg.ldb[0] = NHEAD*HEADD; sg.ldb[1] = NKVH*HEADD; sg.ldb[2] = NKVH*HEADD;
        gemm_f16<<<dim3(QKVN/256, NTOK/128, 1), 256, GEMM_SMEM_BYTES>>>(
            xln1h, HDIM, sg, 0, nullptr, qkvh, QKVN, bqkv, nullptr,
            NTOK, HDIM, nullptr, nullptr, nullptr);
    }

    // 3) RoPE
    {
        int total = NTOK*(NHEAD+NKVH)*64;
        rope_kernel<<<(total+255)/256, 256>>>(qkvh, posids);
    }

    // 4) flash attention (descending q-tiles for load balance)
    flash_kernel<<<dim3(SEQ/64, BATCH*NHEAD), 256, FL_SMEM_BYTES>>>(qkvh, amask, attnh);

    // 5) O projection + residual
    {
        GemmSegs sg;
        sg.end[0] = HDIM; sg.end[1] = HDIM; sg.end[2] = HDIM;
        sg.B[0] = woh; sg.B[1] = woh; sg.B[2] = woh;
        sg.ldb[0] = HDIM; sg.ldb[1] = HDIM; sg.ldb[2] = HDIM;
        gemm_f16<<<dim3(HDIM/256, NTOK/128, 1), 256, GEMM_SMEM_BYTES>>>(
            attnh, NHEAD*HEADD, sg, 0, hbuf, nullptr, HDIM, bo, hidden,
            NTOK, NHEAD*HEADD, nullptr, nullptr, nullptr);
    }

    // 6+7) LN2 with fused gate + top-2 (identical reduction order to old gate)
    ln_kernel<<<NTOK, 256>>>(hbuf, ln2w, ln2b, xln2h, gatew, e01, w01);
    // 8) routing
    cudaMemsetAsync(counts, 0, NEXP*sizeof(int));
    route_count_kernel<<<(NTOK+255)/256, 256>>>(e01, counts, pos01);
    route_offset_kernel<<<1, 32>>>(counts, offsets);
    route_scatter_kernel<<<(NTOK+255)/256, 256>>>(e01, pos01, offsets, toklist, slot01);

    // join 1: w1/w3 ready
    cudaStreamWaitEvent(0, evJoin1, 0);

    // 9) expert up-projections -> fp16 h13
    {
        GemmSegs sg;
        sg.end[0] = FFN; sg.end[1] = 2*FFN; sg.end[2] = 2*FFN;
        sg.B[0] = w1h; sg.B[1] = w3h; sg.B[2] = w3h;
        sg.ldb[0] = FFN; sg.ldb[1] = FFN; sg.ldb[2] = FFN;
        gemm_f16<<<dim3(2*FFN/256, NTOK/128, NEXP), 256, GEMM_SMEM_BYTES>>>(
            xln2h, HDIM, sg, (long long)HDIM*FFN, nullptr, h13h, 2*FFN, nullptr, nullptr,
            NTOK, HDIM, toklist, counts, offsets);
    }

    // 10) act = silu(h1)*h3
    silu_mul_kernel<<<8192, 256>>>(h13h, acth);

    // join 2: w2 ready
    cudaStreamWaitEvent(0, evJoin2, 0);

    // 11) eo = act @ w2(e)
    {
        GemmSegs sg;
        sg.end[0] = HDIM; sg.end[1] = HDIM; sg.end[2] = HDIM;
        sg.B[0] = w2h; sg.B[1] = w2h; sg.B[2] = w2h;
        sg.ldb[0] = HDIM; sg.ldb[1] = HDIM; sg.ldb[2] = HDIM;
        gemm_f16<<<dim3(HDIM/256, NTOK/128, NEXP), 256, GEMM_SMEM_BYTES>>>(
            acth, FFN, sg, (long long)FFN*HDIM, eo, nullptr, HDIM, nullptr, nullptr,
            NTOK, FFN, nullptr, counts, offsets);
    }

    // 12) combine
    combine_kernel<<<(int)(((long long)NTOK*HDIM + 255)/256), 256>>>(hbuf, eo, slot01, w01, out);
}

// round 16
// speedup vs baseline: 1.0376x; 1.0132x over previous
#include <cuda_runtime.h>
#include <cuda_fp16.h>
#include <math.h>
#include <stdint.h>

// ---------------- problem constants ----------------
#define BATCH 2
#define SEQ   1024
#define HDIM  2048
#define NHEAD 16
#define NKVH  4
#define HEADD 128
#define FFN   4096
#define NEXP  8
#define NTOK  (BATCH*SEQ)
#define QKVN  (NHEAD*HEADD + 2*NKVH*HEADD)   // 3072
#define NSLOT (2*NTOK)
#define LNEPS 1e-5f

// ---------------- device scratch ----------------
__device__ __half g_xln1h[NTOK*HDIM];
__device__ __half g_qkvh [NTOK*QKVN];
__device__ __half g_attnh[NTOK*NHEAD*HEADD];
__device__ float  g_h    [NTOK*HDIM];
__device__ __half g_xln2h[NTOK*HDIM];
__device__ __half g_h13h [NSLOT*2*FFN];
__device__ __half g_acth [NSLOT*FFN];
__device__ float  g_eo   [NSLOT*HDIM];
// fp16 weights, ORIGINAL [K][N] layout
__device__ __half g_wqh [HDIM*NHEAD*HEADD];
__device__ __half g_wkh [HDIM*NKVH*HEADD];
__device__ __half g_wvh [HDIM*NKVH*HEADD];
__device__ __half g_woh [HDIM*HDIM];
__device__ __half g_w1h [NEXP*HDIM*FFN];
__device__ __half g_w3h [NEXP*HDIM*FFN];
__device__ __half g_w2h [NEXP*FFN*HDIM];
__device__ float  g_bqkv[QKVN];
// routing
__device__ int   g_e01 [NTOK*2];
__device__ float g_w01 [NTOK*2];
__device__ int   g_pos01[NTOK*2];
__device__ int   g_counts[NEXP];
__device__ int   g_offsets[NEXP];
__device__ int   g_toklist[NSLOT];
__device__ int   g_slot01[NTOK*2];

// ---------------- helpers ----------------
__device__ __forceinline__ void mma_f16(float* c, const uint32_t* a, const uint32_t* b){
    asm volatile(
      "mma.sync.aligned.m16n8k16.row.col.f32.f16.f16.f32 "
      "{%0,%1,%2,%3}, {%4,%5,%6,%7}, {%8,%9}, {%0,%1,%2,%3};\n"
      : "+f"(c[0]), "+f"(c[1]), "+f"(c[2]), "+f"(c[3])
      : "r"(a[0]), "r"(a[1]), "r"(a[2]), "r"(a[3]), "r"(b[0]), "r"(b[1]));
}
__device__ __forceinline__ void ldsm_x4(uint32_t& r0, uint32_t& r1, uint32_t& r2, uint32_t& r3,
                                        uint32_t addr){
    asm volatile("ldmatrix.sync.aligned.m8n8.x4.shared.b16 {%0,%1,%2,%3}, [%4];"
                 : "=r"(r0), "=r"(r1), "=r"(r2), "=r"(r3) : "r"(addr));
}
__device__ __forceinline__ void ldsm_x4_t(uint32_t& r0, uint32_t& r1, uint32_t& r2, uint32_t& r3,
                                          uint32_t addr){
    asm volatile("ldmatrix.sync.aligned.m8n8.x4.trans.shared.b16 {%0,%1,%2,%3}, [%4];"
                 : "=r"(r0), "=r"(r1), "=r"(r2), "=r"(r3) : "r"(addr));
}
__device__ __forceinline__ void cpa16h(__half* smem, const __half* gmem, bool pred){
    uint32_t s = (uint32_t)__cvta_generic_to_shared(smem);
    int sz = pred ? 16 : 0;
    asm volatile("cp.async.cg.shared.global [%0], [%1], 16, %2;\n"
                 :: "r"(s), "l"(gmem), "r"(sz));
}
#define CP_COMMIT() asm volatile("cp.async.commit_group;\n")
template<int N> __device__ __forceinline__ void cp_wait(){
    asm volatile("cp.async.wait_group %0;\n" :: "n"(N));
}

__device__ __forceinline__ float block_sum_256(float v){
    __shared__ float red[8];
    __shared__ float total;
    #pragma unroll
    for (int o = 16; o; o >>= 1) v += __shfl_xor_sync(0xffffffffu, v, o);
    if ((threadIdx.x & 31) == 0) red[threadIdx.x >> 5] = v;
    __syncthreads();
    if (threadIdx.x == 0){
        float s = 0.f;
        #pragma unroll
        for (int i = 0; i < 8; i++) s += red[i];
        total = s;
    }
    __syncthreads();
    float r = total;
    __syncthreads();
    return r;
}

// ---------------- streaming fp32 -> fp16 convert ----------------
__global__ __launch_bounds__(256)
void cvt16(const float4* __restrict__ src, uint4* __restrict__ dst, long long n8){
    for (long long i = blockIdx.x*256LL + threadIdx.x; i < n8; i += gridDim.x*256LL){
        float4 v0 = src[2*i], v1 = src[2*i+1];
        __half2 a = __floats2half2_rn(v0.x, v0.y);
        __half2 b = __floats2half2_rn(v0.z, v0.w);
        __half2 c = __floats2half2_rn(v1.x, v1.y);
        __half2 d = __floats2half2_rn(v1.z, v1.w);
        uint4 o;
        o.x = *(uint32_t*)&a; o.y = *(uint32_t*)&b;
        o.z = *(uint32_t*)&c; o.w = *(uint32_t*)&d;
        dst[i] = o;
    }
}

__global__ void concat_bias(const float* bq, const float* bk, const float* bv, float* dst){
    int i = blockIdx.x*256 + threadIdx.x;
    if (i < NHEAD*HEADD) dst[i] = bq[i];
    else if (i < NHEAD*HEADD + NKVH*HEADD) dst[i] = bk[i - NHEAD*HEADD];
    else if (i < QKVN) dst[i] = bv[i - NHEAD*HEADD - NKVH*HEADD];
}

// ---------------- LayerNorm (+ optional fused MoE gate / top-2) ----------------
__global__ __launch_bounds__(256)
void ln_kernel(const float* __restrict__ x, const float* __restrict__ w,
               const float* __restrict__ b, __half* __restrict__ yh,
               const float* __restrict__ gw,
               int* __restrict__ e01, float* __restrict__ w01){
    long long row = blockIdx.x;
    const float* xr = x + row * HDIM;
    float v[8]; float s = 0.f;
    #pragma unroll
    for (int i = 0; i < 8; i++){ v[i] = xr[threadIdx.x + 256*i]; s += v[i]; }
    float mean = block_sum_256(s) * (1.f/HDIM);
    float ss = 0.f;
    #pragma unroll
    for (int i = 0; i < 8; i++){ float d = v[i]-mean; ss += d*d; }
    float var = block_sum_256(ss) * (1.f/HDIM);
    float rstd = rsqrtf(var + LNEPS);
    float ov[8];
    #pragma unroll
    for (int i = 0; i < 8; i++){
        int c = threadIdx.x + 256*i;
        ov[i] = (v[i]-mean)*rstd*w[c] + b[c];
        yh[row*HDIM + c] = __float2half(ov[i]);
    }
    if (gw){
        float part[NEXP];
        #pragma unroll
        for (int e = 0; e < NEXP; e++) part[e] = 0.f;
        #pragma unroll
        for (int i = 0; i < 8; i++){
            int c = threadIdx.x + 256*i;
            const float* gp = gw + (long long)c*NEXP;
            #pragma unroll
            for (int e = 0; e < NEXP; e++) part[e] += ov[i]*gp[e];
        }
        __shared__ float red[8][NEXP];
        #pragma unroll
        for (int e = 0; e < NEXP; e++){
            float vv = part[e];
            #pragma unroll
            for (int o = 16; o; o >>= 1) vv += __shfl_xor_sync(0xffffffffu, vv, o);
            if ((threadIdx.x & 31) == 0) red[threadIdx.x >> 5][e] = vv;
        }
        __syncthreads();
        if (threadIdx.x == 0){
            float lg[NEXP];
            #pragma unroll
            for (int e = 0; e < NEXP; e++){
                float ssum = 0.f;
                #pragma unroll
                for (int w8 = 0; w8 < 8; w8++) ssum += red[w8][e];
                lg[e] = ssum;
            }
            int b0 = 0;
            #pragma unroll
            for (int e = 1; e < NEXP; e++) if (lg[e] > lg[b0]) b0 = e;
            int b1 = -1;
            #pragma unroll
            for (int e = 0; e < NEXP; e++)
                if (e != b0 && (b1 < 0 || lg[e] > lg[b1])) b1 = e;
            float t0 = 1.f / (1.f + expf(lg[b1] - lg[b0]));
            e01[2*row] = b0; e01[2*row+1] = b1;
            w01[2*row] = t0; w01[2*row+1] = 1.f - t0;
        }
    }
}

// ---------------- fp16 GEMM: ldmatrix A + ldmatrix.trans B ----------------
struct GemmSegs {
    int end[3];
    const __half* B[3];
    int ldb[3];
};

#define GA_STG (128*40)
#define GB_STG (32*264)
#define GB_BASE (3*GA_STG)
#define GEMM_SMEM_BYTES ((GB_BASE + 3*GB_STG)*2)

__global__ __launch_bounds__(256)
void gemm_f16(const __half* __restrict__ A, int lda,
              GemmSegs segs, long long bStride,
              float* __restrict__ Cf, __half* __restrict__ Ch, int ldc,
              const float* __restrict__ bias, const float* __restrict__ resid,
              int M, int K,
              const int* __restrict__ rowidx,
              const int* __restrict__ counts,
              const int* __restrict__ offsets)
{
    extern __shared__ __half hsm[];
#define ASH(st, r, c) hsm[(st)*GA_STG + (r)*40 + (c)]
#define BSH(st, k, c) hsm[GB_BASE + (st)*GB_STG + (k)*264 + (c)]

    int e = blockIdx.z;
    int rowStart = 0, Mm = M;
    if (counts){ Mm = counts[e]; rowStart = offsets[e]; }
    int mbase = blockIdx.y * 128;
    if (mbase >= Mm) return;
    int nbase = blockIdx.x * 256;

    int s = 0;
    if (nbase >= segs.end[0]) s = 1;
    if (nbase >= segs.end[1]) s = 2;
    int segStart = (s == 0) ? 0 : segs.end[s-1];
    int ln = nbase - segStart;
    const __half* Bp = segs.B[s] + (long long)e * bStride + ln;
    int ldb = segs.ldb[s];

    int tid  = threadIdx.x;
    int lane = tid & 31, wid = tid >> 5;
    int warpM = wid >> 2, warpN = wid & 3;
    int g = lane >> 2, t4 = lane & 3;

    int ar = tid >> 1, hsel = tid & 1;
    bool aval = (mbase + ar < Mm);
    int arow = 0;
    if (aval) arow = rowidx ? rowidx[rowStart + mbase + ar] : (rowStart + mbase + ar);
    const __half* aptr = A + (long long)arow * lda + hsel*16;
    int brow = tid >> 3, bch = tid & 7;

    uint32_t smbase = (uint32_t)__cvta_generic_to_shared(hsm);
    int a_m = (lane & 7) + 8*((lane >> 3) & 1);
    int a_k = 8*((lane >> 4) & 1);
    uint32_t asm0 = smbase + (uint32_t)((warpM*64 + a_m)*40 + a_k)*2;
    int k_off = (lane & 7) + 8*((lane >> 3) & 1);
    int c_off = warpN*64 + 8*((lane >> 4) & 1);
    uint32_t bsm0 = smbase + GB_BASE*2 + (uint32_t)(k_off*264 + c_off)*2;

    float acc[32][4];
    #pragma unroll
    for (int i = 0; i < 32; i++)
        #pragma unroll
        for (int j = 0; j < 4; j++) acc[i][j] = 0.f;

    int nk = K >> 5;

#define GEMM_ISSUE(KT, ST) do {                                               \
        cpa16h(&ASH(ST, ar, hsel*16),     aptr + (KT)*32,     aval);          \
        cpa16h(&ASH(ST, ar, hsel*16 + 8), aptr + (KT)*32 + 8, aval);          \
        _Pragma("unroll")                                                     \
        for (int i = 0; i < 4; i++){                                          \
            int c8 = (bch + 8*i)*8;                                           \
            cpa16h(&BSH(ST, brow, c8),                                        \
                   Bp + (long long)((KT)*32 + brow)*ldb + c8, true);          \
        }                                                                     \
    } while(0)

    GEMM_ISSUE(0, 0); CP_COMMIT();
    GEMM_ISSUE(1, 1); CP_COMMIT();

    int cur = 0;
    for (int kt = 0; kt < nk; ++kt){
        if (kt + 1 < nk) cp_wait<1>(); else cp_wait<0>();
        __syncthreads();
        if (kt + 2 < nk){
            int nxt = cur + 2; if (nxt >= 3) nxt -= 3;
            GEMM_ISSUE(kt+2, nxt); CP_COMMIT();
        }

        #pragma unroll
        for (int ks = 0; ks < 2; ++ks){
            uint32_t af[4][4], bf[8][2];
            uint32_t aadr = asm0 + (uint32_t)cur*(GA_STG*2) + (uint32_t)(ks*16*2);
            #pragma unroll
            for (int ma = 0; ma < 4; ma++){
                ldsm_x4(af[ma][0], af[ma][1], af[ma][2], af[ma][3],
                        aadr + (uint32_t)(ma*16*40*2));
            }
            uint32_t badr = bsm0 + (uint32_t)cur*(GB_STG*2) + (uint32_t)(ks*16*264*2);
            #pragma unroll
            for (int p = 0; p < 4; p++){
                ldsm_x4_t(bf[2*p][0], bf[2*p][1], bf[2*p+1][0], bf[2*p+1][1],
                          badr + (uint32_t)(p*16*2));
            }
            #pragma unroll
            for (int ma = 0; ma < 4; ma++)
                #pragma unroll
                for (int na = 0; na < 8; na++)
                    mma_f16(acc[ma*8+na], af[ma], bf[na]);
        }
        cur = cur + 1; if (cur >= 3) cur -= 3;
    }

    #pragma unroll
    for (int ma = 0; ma < 4; ma++){
        #pragma unroll
        for (int na = 0; na < 8; na++){
            float* a4 = acc[ma*8+na];
            #pragma unroll
            for (int half_ = 0; half_ < 2; half_++){
                int lrow = warpM*64 + ma*16 + g + (half_ ? 8 : 0);
                int gcol = nbase + warpN*64 + na*8 + 2*t4;
                int gr = mbase + lrow;
                if (gr < Mm){
                    long long orow = rowStart + gr;
                    float v0 = a4[half_*2+0];
                    float v1 = a4[half_*2+1];
                    if (bias){ v0 += bias[gcol]; v1 += bias[gcol+1]; }
                    if (resid){
                        const float* rp = &resid[orow*(long long)ldc + gcol];
                        v0 += rp[0]; v1 += rp[1];
                    }
                    if (Cf){
                        *(float2*)&Cf[orow*(long long)ldc + gcol] = make_float2(v0, v1);
                    } else {
                        *(__half2*)&Ch[orow*(long long)ldc + gcol] = __floats2half2_rn(v0, v1);
                    }
                }
            }
        }
    }
#undef ASH
#undef BSH
#undef GEMM_ISSUE
}

// ---------------- RoPE ----------------
__global__ __launch_bounds__(256)
void rope_kernel(__half* __restrict__ qkv, const int* __restrict__ pos_ids){
    int idx = blockIdx.x*256 + threadIdx.x;
    const int total = NTOK*(NHEAD+NKVH)*64;
    if (idx >= total) return;
    int j    = idx & 63;
    int rest = idx >> 6;
    int head = rest % (NHEAD+NKVH);
    int t    = rest / (NHEAD+NKVH);
    __half* p;
    if (head < NHEAD) p = qkv + (long long)t*QKVN + head*HEADD;
    else              p = qkv + (long long)t*QKVN + NHEAD*HEADD + (head-NHEAD)*HEADD;
    double inv = exp((double)j * -0.21586735246819178);
    float th = (float)pos_ids[t] * (float)inv;
    float sn, cs; sincosf(th, &sn, &cs);
    float x0 = __half2float(p[j]), x1 = __half2float(p[j+64]);
    p[j]    = __float2half(x0*cs - x1*sn);
    p[j+64] = __float2half(x1*cs + x0*sn);
}

// ---------------- fp16 tensor-core flash attention (k-tile 64) ----------------
#define FKT 64
#define FL_PS_F   (64*68)
#define FL_FLOATS (FL_PS_F + 64*3 + 64)
#define FL_QS_H   0
#define FL_KS_H   (64*136)
#define FL_VS_H   (2*64*136)
#define FL_PH_H   (3*64*136)
#define FL_HALVES (FL_PH_H + 64*72)
#define FL_SMEM_BYTES (FL_FLOATS*4 + FL_HALVES*2)

__global__ __launch_bounds__(256, 2)
void flash_kernel(const __half* __restrict__ qkv, const int* __restrict__ amask,
                  __half* __restrict__ O)
{
    extern __shared__ float sm[];
    float* Ps   = sm;
    float* mrow = sm + FL_PS_F;
    float* lrow = mrow + 64;
    float* srow = lrow + 64;
    int*   mk   = (int*)(srow + 64);
    __half* hb  = (__half*)(sm + FL_FLOATS);
    __half* Qs = hb + FL_QS_H;     // [64][136]
    __half* Ks = hb + FL_KS_H;     // [64][136]
    __half* Vs = hb + FL_VS_H;     // [64][136]
    __half* Ph = hb + FL_PH_H;     // [64][72]

    int qt = (gridDim.x - 1) - blockIdx.x;   // heavy causal tiles start first
    int bh = blockIdx.y;
    int b  = bh >> 4, h = bh & 15;
    int kvh = h >> 2;
    int tid = threadIdx.x;
    int lane = tid & 31, wid = tid >> 5;
    int g = lane >> 2, t4 = lane & 3;
    int mS = wid & 3;      // 16-row slab
    int nH = wid >> 2;     // S: 32-col half ; PV: 64-col half

    int vk = (lane & 7) + 8*((lane >> 3) & 1);
    int vc = 8*((lane >> 4) & 1);
    uint32_t vbase = (uint32_t)__cvta_generic_to_shared(Vs) + (uint32_t)(vk*136 + 64*nH + vc)*2;

    for (int e2 = tid; e2 < 64*64; e2 += 256){
        int row = e2 >> 6; int d2 = (e2 & 63)*2;
        *(uint32_t*)&Qs[row*136 + d2] =
            *(const uint32_t*)&qkv[(long long)(b*SEQ + qt*64 + row)*QKVN + h*HEADD + d2];
    }
    if (tid < 64){ mrow[tid] = -1e30f; lrow[tid] = 0.f; }

    float oacc[8][4];
    #pragma unroll
    for (int i = 0; i < 8; i++)
        #pragma unroll
        for (int j = 0; j < 4; j++) oacc[i][j] = 0.f;

    const float iscale = 0.08838834764831843f;

    int nkt = qt + 1;   // k-tiles of 64
    for (int kt = 0; kt < nkt; ++kt){
        __syncthreads();
        for (int e2 = tid; e2 < FKT*64; e2 += 256){
            int kk = e2 >> 6; int d2 = (e2 & 63)*2;
            long long base = (long long)(b*SEQ + kt*FKT + kk)*QKVN + NHEAD*HEADD + kvh*HEADD;
            *(uint32_t*)&Ks[kk*136 + d2] = *(const uint32_t*)&qkv[base + d2];
            *(uint32_t*)&Vs[kk*136 + d2] = *(const uint32_t*)&qkv[base + NKVH*HEADD + d2];
        }
        if (tid < FKT) mk[tid] = amask[b*SEQ + kt*FKT + tid];
        __syncthreads();

        // S = Q @ K^T : warp computes 16 rows x 32 cols
        float sacc[4][4];
        #pragma unroll
        for (int i = 0; i < 4; i++)
            #pragma unroll
            for (int j = 0; j < 4; j++) sacc[i][j] = 0.f;
        #pragma unroll
        for (int ks = 0; ks < 8; ++ks){
            int k0 = ks*16;
            uint32_t a[4];
            int r = 16*mS;
            a[0] = *(const uint32_t*)&Qs[(r+g  )*136 + k0 + 2*t4    ];
            a[1] = *(const uint32_t*)&Qs[(r+g+8)*136 + k0 + 2*t4    ];
            a[2] = *(const uint32_t*)&Qs[(r+g  )*136 + k0 + 2*t4 + 8];
            a[3] = *(const uint32_t*)&Qs[(r+g+8)*136 + k0 + 2*t4 + 8];
            #pragma unroll
            for (int j = 0; j < 4; j++){
                int c = 32*nH + 8*j + g;
                uint32_t bfr[2];
                bfr[0] = *(const uint32_t*)&Ks[c*136 + k0 + 2*t4    ];
                bfr[1] = *(const uint32_t*)&Ks[c*136 + k0 + 2*t4 + 8];
                mma_f16(sacc[j], a, bfr);
            }
        }
        #pragma unroll
        for (int j = 0; j < 4; j++){
            #pragma unroll
            for (int cr = 0; cr < 4; cr++){
                int row = 16*mS + g + ((cr >= 2) ? 8 : 0);
                int col = 32*nH + 8*j + 2*t4 + (cr & 1);
                int sq = qt*64 + row, sk = kt*FKT + col;
                float vv = sacc[j][cr]*iscale;
                if (sk > sq || mk[col] == 0) vv = -1e30f;
                Ps[row*68 + col] = vv;
            }
        }
        __syncthreads();

        if (tid < 64){
            int r = tid;
            float mo = mrow[r], mx = mo;
            #pragma unroll 8
            for (int kk = 0; kk < FKT; kk++) mx = fmaxf(mx, Ps[r*68+kk]);
            float sc = __expf(mo - mx);
            float ssum = 0.f;
            #pragma unroll 8
            for (int kk = 0; kk < FKT; kk++){
                float p = __expf(Ps[r*68+kk] - mx);
                ssum += p;
                Ph[r*72+kk] = __float2half(p);
            }
            lrow[r] = lrow[r]*sc + ssum;
            mrow[r] = mx;
            srow[r] = sc;
        }
        __syncthreads();

        {
            float sc0 = srow[16*mS + g];
            float sc1 = srow[16*mS + g + 8];
            #pragma unroll
            for (int j = 0; j < 8; j++){
                oacc[j][0] *= sc0; oacc[j][1] *= sc0;
                oacc[j][2] *= sc1; oacc[j][3] *= sc1;
            }
        }
        #pragma unroll
        for (int ks = 0; ks < 4; ++ks){
            int k0 = ks*16 + 2*t4;
            uint32_t a[4];
            int r = 16*mS;
            a[0] = *(const uint32_t*)&Ph[(r+g  )*72 + k0    ];
            a[1] = *(const uint32_t*)&Ph[(r+g+8)*72 + k0    ];
            a[2] = *(const uint32_t*)&Ph[(r+g  )*72 + k0 + 8];
            a[3] = *(const uint32_t*)&Ph[(r+g+8)*72 + k0 + 8];
            uint32_t badr = vbase + (uint32_t)(ks*16*136*2);
            uint32_t bf[8][2];
            #pragma unroll
            for (int p = 0; p < 4; p++){
                ldsm_x4_t(bf[2*p][0], bf[2*p][1], bf[2*p+1][0], bf[2*p+1][1],
                          badr + (uint32_t)(p*16*2));
            }
            #pragma unroll
            for (int j = 0; j < 8; j++)
                mma_f16(oacc[j], a, bf[j]);
        }
    }

    #pragma unroll
    for (int j = 0; j < 8; j++){
        #pragma unroll
        for (int half_ = 0; half_ < 2; half_++){
            int row = 16*mS + g + (half_ ? 8 : 0);
            int col = 64*nH + 8*j + 2*t4;
            int sq = qt*64 + row;
            float inv = 1.f / lrow[row];
            __half2 o2 = __floats2half2_rn(oacc[j][half_*2+0]*inv, oacc[j][half_*2+1]*inv);
            *(__half2*)&O[(((long long)(b*SEQ + sq))*NHEAD + h)*HEADD + col] = o2;
        }
    }
}

// ---------------- routing ----------------
__global__ void route_count_kernel(const int* __restrict__ e01,
                                   int* __restrict__ counts, int* __restrict__ pos01){
    int t = blockIdx.x*blockDim.x + threadIdx.x;
    if (t < NTOK){
        pos01[2*t]   = atomicAdd(&counts[e01[2*t]],   1);
        pos01[2*t+1] = atomicAdd(&counts[e01[2*t+1]], 1);
    }
}
__global__ void route_offset_kernel(const int* __restrict__ counts, int* __restrict__ offsets){
    if (threadIdx.x == 0 && blockIdx.x == 0){
        int s = 0;
        for (int e = 0; e < NEXP; e++){ offsets[e] = s; s += counts[e]; }
    }
}
__global__ void route_scatter_kernel(const int* __restrict__ e01, const int* __restrict__ pos01,
                                     const int* __restrict__ offsets,
                                     int* __restrict__ toklist, int* __restrict__ slot01){
    int t = blockIdx.x*blockDim.x + threadIdx.x;
    if (t < NTOK){
        #pragma unroll
        for (int j = 0; j < 2; j++){
            int sl = offsets[e01[2*t+j]] + pos01[2*t+j];
            toklist[sl] = t;
            slot01[2*t+j] = sl;
        }
    }
}

// ---------------- act = silu(h1)*h3 ----------------
__global__ __launch_bounds__(256)
void silu_mul_kernel(const __half* __restrict__ h13, __half* __restrict__ act){
    long long n2 = (long long)NSLOT*FFN/2;
    for (long long i = blockIdx.x*256LL + threadIdx.x; i < n2; i += gridDim.x*256LL){
        long long slot = i >> 11;
        int f2 = (int)(i & (FFN/2 - 1));
        __half2 a = *(const __half2*)&h13[slot*(2*FFN) + f2*2];
        __half2 c = *(const __half2*)&h13[slot*(2*FFN) + FFN + f2*2];
        float v0 = __half2float(a.x), v1 = __half2float(a.y);
        float u0 = __half2float(c.x), u1 = __half2float(c.y);
        float r0 = v0 / (1.f + expf(-v0)) * u0;
        float r1 = v1 / (1.f + expf(-v1)) * u1;
        *(__half2*)&act[i*2] = __floats2half2_rn(r0, r1);
    }
}

// ---------------- final combine ----------------
__global__ __launch_bounds__(256)
void combine_kernel(const float* __restrict__ h, const float* __restrict__ eo,
                    const int* __restrict__ slot01, const float* __restrict__ w01,
                    float* __restrict__ out){
    long long idx = blockIdx.x*256LL + threadIdx.x;
    if (idx >= (long long)NTOK*HDIM) return;
    int t = (int)(idx >> 11);
    int c = (int)(idx & 2047);
    float v = h[idx];
    v += w01[2*t]   * eo[(long long)slot01[2*t]  *HDIM + c];
    v += w01[2*t+1] * eo[(long long)slot01[2*t+1]*HDIM + c];
    out[idx] = v;
}

// ---------------- launch ----------------
extern "C" void kernel_launch(void* const* d_in, const int* in_sizes, int n_in,
                              void* d_out, int out_size){
    const float* hidden = (const float*)d_in[0];
    const int*   amask  = (const int*)  d_in[1];
    const int*   posids = (const int*)  d_in[2];
    const float* ln1w = (const float*)d_in[3];
    const float* ln1b = (const float*)d_in[4];
    const float* ln2w = (const float*)d_in[5];
    const float* ln2b = (const float*)d_in[6];
    const float* wq = (const float*)d_in[7];
    const float* bq = (const float*)d_in[8];
    const float* wk = (const float*)d_in[9];
    const float* bk = (const float*)d_in[10];
    const float* wv = (const float*)d_in[11];
    const float* bv = (const float*)d_in[12];
    const float* wo = (const float*)d_in[13];
    const float* bo = (const float*)d_in[14];
    const float* gatew = (const float*)d_in[15];
    const float* w1 = (const float*)d_in[16];
    const float* w2 = (const float*)d_in[17];
    const float* w3 = (const float*)d_in[18];
    float* out = (float*)d_out;

    __half *xln1h, *qkvh, *attnh, *xln2h, *h13h, *acth;
    __half *wqh, *wkh, *wvh, *woh, *w1h, *w3h, *w2h;
    float *hbuf, *eo, *w01, *bqkv;
    int *e01, *pos01, *counts, *offsets, *toklist, *slot01;
    cudaGetSymbolAddress((void**)&xln1h, g_xln1h);
    cudaGetSymbolAddress((void**)&qkvh, g_qkvh);
    cudaGetSymbolAddress((void**)&attnh, g_attnh);
    cudaGetSymbolAddress((void**)&hbuf, g_h);
    cudaGetSymbolAddress((void**)&xln2h, g_xln2h);
    cudaGetSymbolAddress((void**)&h13h, g_h13h);
    cudaGetSymbolAddress((void**)&acth, g_acth);
    cudaGetSymbolAddress((void**)&eo, g_eo);
    cudaGetSymbolAddress((void**)&wqh, g_wqh);
    cudaGetSymbolAddress((void**)&wkh, g_wkh);
    cudaGetSymbolAddress((void**)&wvh, g_wvh);
    cudaGetSymbolAddress((void**)&woh, g_woh);
    cudaGetSymbolAddress((void**)&w1h, g_w1h);
    cudaGetSymbolAddress((void**)&w3h, g_w3h);
    cudaGetSymbolAddress((void**)&w2h, g_w2h);
    cudaGetSymbolAddress((void**)&bqkv, g_bqkv);
    cudaGetSymbolAddress((void**)&e01, g_e01);
    cudaGetSymbolAddress((void**)&w01, g_w01);
    cudaGetSymbolAddress((void**)&pos01, g_pos01);
    cudaGetSymbolAddress((void**)&counts, g_counts);
    cudaGetSymbolAddress((void**)&offsets, g_offsets);
    cudaGetSymbolAddress((void**)&toklist, g_toklist);
    cudaGetSymbolAddress((void**)&slot01, g_slot01);

    cudaFuncSetAttribute(flash_kernel, cudaFuncAttributeMaxDynamicSharedMemorySize, FL_SMEM_BYTES);
    cudaFuncSetAttribute(gemm_f16,    cudaFuncAttributeMaxDynamicSharedMemorySize, GEMM_SMEM_BYTES);

    static cudaStream_t s2 = nullptr;
    static cudaEvent_t evFork = nullptr, evJoin1 = nullptr, evJoin2 = nullptr;
    if (!s2){
        cudaStreamCreateWithFlags(&s2, cudaStreamNonBlocking);
        cudaEventCreateWithFlags(&evFork, cudaEventDisableTiming);
        cudaEventCreateWithFlags(&evJoin1, cudaEventDisableTiming);
        cudaEventCreateWithFlags(&evJoin2, cudaEventDisableTiming);
    }

    auto cvt = [&](cudaStream_t st, const float* s, __half* d, long long n){
        long long n8 = n >> 3;
        int nb = (int)((n8 + 255) / 256);
        if (nb > 32768) nb = 32768;
        cvt16<<<nb, 256, 0, st>>>((const float4*)s, (uint4*)d, n8);
    };

    // 0a) attention weights on main stream
    cvt(0, wq, wqh, (long long)HDIM*NHEAD*HEADD);
    cvt(0, wk, wkh, (long long)HDIM*NKVH*HEADD);
    cvt(0, wv, wvh, (long long)HDIM*NKVH*HEADD);
    cvt(0, wo, woh, (long long)HDIM*HDIM);
    concat_bias<<<(QKVN+255)/256, 256>>>(bq, bk, bv, bqkv);

    // 0b) fork: MoE conversion on side stream; split joins
    cudaEventRecord(evFork, 0);
    cudaStreamWaitEvent(s2, evFork, 0);
    cvt(s2, w1, w1h, (long long)NEXP*HDIM*FFN);
    cvt(s2, w3, w3h, (long long)NEXP*HDIM*FFN);
    cudaEventRecord(evJoin1, s2);
    cvt(s2, w2, w2h, (long long)NEXP*FFN*HDIM);
    cudaEventRecord(evJoin2, s2);

    // 1) LN1 (no gate)
    ln_kernel<<<NTOK, 256>>>(hidden, ln1w, ln1b, xln1h, nullptr, nullptr, nullptr);

    // 2) fused QKV projection
    {
        GemmSegs sg;
        sg.end[0] = NHEAD*HEADD; sg.end[1] = NHEAD*HEADD + NKVH*HEADD; sg.end[2] = QKVN;
        sg.B[0] = wqh; sg.B[1] = wkh; sg.B[2] = wvh;
        sg.ldb[0] = NHEAD*HEADD; sg.ldb[1] = NKVH*HEADD; sg.ldb[2] = NKVH*HEADD;
        gemm_f16<<<dim3(QKVN/256, NTOK/128, 1), 256, GEMM_SMEM_BYTES>>>(
            xln1h, HDIM, sg, 0, nullptr, qkvh, QKVN, bqkv, nullptr,
            NTOK, HDIM, nullptr, nullptr, nullptr);
    }

    // 3) RoPE
    {
        int total = NTOK*(NHEAD+NKVH)*64;
        rope_kernel<<<(total+255)/256, 256>>>(qkvh, posids);
    }

    // 4) flash attention (k-tile 64, descending q-tiles)
    flash_kernel<<<dim3(SEQ/64, BATCH*NHEAD), 256, FL_SMEM_BYTES>>>(qkvh, amask, attnh);

    // 5) O projection + residual
    {
        GemmSegs sg;
        sg.end[0] = HDIM; sg.end[1] = HDIM; sg.end[2] = HDIM;
        sg.B[0] = woh; sg.B[1] = woh; sg.B[2] = woh;
        sg.ldb[0] = HDIM; sg.ldb[1] = HDIM; sg.ldb[2] = HDIM;
        gemm_f16<<<dim3(HDIM/256, NTOK/128, 1), 256, GEMM_SMEM_BYTES>>>(
            attnh, NHEAD*HEADD, sg, 0, hbuf, nullptr, HDIM, bo, hidden,
            NTOK, NHEAD*HEADD, nullptr, nullptr, nullptr);
    }

    // 6+7) LN2 with fused gate + top-2
    ln_kernel<<<NTOK, 256>>>(hbuf, ln2w, ln2b, xln2h, gatew, e01, w01);
    // 8) routing
    cudaMemsetAsync(counts, 0, NEXP*sizeof(int));
    route_count_kernel<<<(NTOK+255)/256, 256>>>(e01, counts, pos01);
    route_offset_kernel<<<1, 32>>>(counts, offsets);
    route_scatter_kernel<<<(NTOK+255)/256, 256>>>(e01, pos01, offsets, toklist, slot01);

    // join 1: w1/w3 ready
    cudaStreamWaitEvent(0, evJoin1, 0);

    // 9) expert up-projections -> fp16 h13
    {
        GemmSegs sg;
        sg.end[0] = FFN; sg.end[1] = 2*FFN; sg.end[2] = 2*FFN;
        sg.B[0] = w1h; sg.B[1] = w3h; sg.B[2] = w3h;
        sg.ldb[0] = FFN; sg.ldb[1] = FFN; sg.ldb[2] = FFN;
        gemm_f16<<<dim3(2*FFN/256, NTOK/128, NEXP), 256, GEMM_SMEM_BYTES>>>(
            xln2h, HDIM, sg, (long long)HDIM*FFN, nullptr, h13h, 2*FFN, nullptr, nullptr,
            NTOK, HDIM, toklist, counts, offsets);
    }

    // 10) act = silu(h1)*h3
    silu_mul_kernel<<<8192, 256>>>(h13h, acth);

    // join 2: w2 ready
    cudaStreamWaitEvent(0, evJoin2, 0);

    // 11) eo = act @ w2(e)
    {
        GemmSegs sg;
        sg.end[0] = HDIM; sg.end[1] = HDIM; sg.end[2] = HDIM;
        sg.B[0] = w2h; sg.B[1] = w2h; sg.B[2] = w2h;
        sg.ldb[0] = HDIM; sg.ldb[1] = HDIM; sg.ldb[2] = HDIM;
        gemm_f16<<<dim3(HDIM/256, NTOK/128, NEXP), 256, GEMM_SMEM_BYTES>>>(
            acth, FFN, sg, (long long)FFN*HDIM, eo, nullptr, HDIM, nullptr, nullptr,
            NTOK, FFN, nullptr, counts, offsets);
    }

    // 12) combine
    combine_kernel<<<(int)(((long long)NTOK*HDIM + 255)/256), 256>>>(hbuf, eo, slot01, w01, out);
}